// round 1
// baseline (speedup 1.0000x reference)
#include <cuda_runtime.h>
#include <math.h>

#define Bn 8192
#define Dn 1024
#define En 16
#define Hn 1024
#define TOPK 8

// ---------------- scratch (static device allocations are allowed) ----------
__device__ float g_clean[Bn * En];
__device__ float g_stddev[Bn * En];
__device__ float g_noisy[Bn * En];
__device__ float g_gates[Bn * En];
__device__ float g_importance[En];
__device__ float g_load[En];

// ---------------- kernel 0: zero accumulators ------------------------------
__global__ void k_init() {
    int t = threadIdx.x;
    if (t < En) { g_importance[t] = 0.f; g_load[t] = 0.f; }
}

// ---------------- kernel 1: gating logits ----------------------------------
// one block per row; warps 0..15 -> clean logits, warps 16..31 -> raw noise
__global__ __launch_bounds__(1024) void k_logits(
    const float* __restrict__ x, const float* __restrict__ wg,
    const float* __restrict__ wn, const float* __restrict__ noise)
{
    int b = blockIdx.x;
    __shared__ float xs[Dn];
    __shared__ float part[32];
    int tid = threadIdx.x;
    for (int i = tid; i < Dn; i += 1024) xs[i] = x[(size_t)b * Dn + i];
    __syncthreads();

    int w = tid >> 5, lane = tid & 31;
    int e = w & 15;
    const float* __restrict__ W = (w < 16) ? wg : wn;
    float s = 0.f;
    #pragma unroll
    for (int it = 0; it < Dn / 32; it++) {
        int i = lane + it * 32;
        s += xs[i] * W[i * En + e];
    }
    #pragma unroll
    for (int off = 16; off; off >>= 1) s += __shfl_down_sync(0xffffffffu, s, off);
    if (lane == 0) part[w] = s;
    __syncthreads();

    if (tid < 16) {
        float clean = part[tid];
        float raw   = part[tid + 16];
        // stable softplus
        float sp = fmaxf(raw, 0.f) + log1pf(expf(-fabsf(raw)));
        float sd = sp + 0.01f;
        float nz = clean + noise[b * En + tid] * sd;
        g_clean[b * En + tid]  = clean;
        g_stddev[b * En + tid] = sd;
        g_noisy[b * En + tid]  = nz;
    }
}

// ---------------- kernel 2: softmax / top-9 / gates / load -----------------
__global__ __launch_bounds__(256) void k_gate()
{
    int b = blockIdx.x * 256 + threadIdx.x;
    int lane = threadIdx.x & 31;

    float nz[16], cl[16], sd[16];
    #pragma unroll
    for (int i = 0; i < 4; i++) {
        float4 v = ((const float4*)(g_noisy  + (size_t)b * 16))[i];
        nz[4*i] = v.x; nz[4*i+1] = v.y; nz[4*i+2] = v.z; nz[4*i+3] = v.w;
        float4 c = ((const float4*)(g_clean  + (size_t)b * 16))[i];
        cl[4*i] = c.x; cl[4*i+1] = c.y; cl[4*i+2] = c.z; cl[4*i+3] = c.w;
        float4 s = ((const float4*)(g_stddev + (size_t)b * 16))[i];
        sd[4*i] = s.x; sd[4*i+1] = s.y; sd[4*i+2] = s.z; sd[4*i+3] = s.w;
    }

    // softmax over 16
    float m = nz[0];
    #pragma unroll
    for (int e = 1; e < 16; e++) m = fmaxf(m, nz[e]);
    float p[16], sum = 0.f;
    #pragma unroll
    for (int e = 0; e < 16; e++) { p[e] = expf(nz[e] - m); sum += p[e]; }
    float inv = 1.f / sum;
    #pragma unroll
    for (int e = 0; e < 16; e++) p[e] *= inv;

    // top-9 selection (strict > keeps lowest index on ties, matching jax)
    float topv[9]; int topi[9]; unsigned mask = 0;
    #pragma unroll
    for (int t = 0; t < 9; t++) {
        float best = -1.f; int bi = 0;
        #pragma unroll
        for (int e = 0; e < 16; e++) {
            bool ok = (!((mask >> e) & 1u)) && (p[e] > best);
            if (ok) { best = p[e]; bi = e; }
        }
        topv[t] = best; topi[t] = bi; mask |= (1u << bi);
    }

    float ksum = 0.f;
    #pragma unroll
    for (int t = 0; t < 8; t++) ksum += topv[t];
    float dinv = 1.f / (ksum + 1e-6f);

    float g16[16];
    #pragma unroll
    for (int e = 0; e < 16; e++) {
        float ge = 0.f;
        #pragma unroll
        for (int t = 0; t < 8; t++) ge = (topi[t] == e) ? topv[t] * dinv : ge;
        g16[e] = ge;
    }

    // write gates row
    #pragma unroll
    for (int i = 0; i < 4; i++) {
        ((float4*)(g_gates + (size_t)b * 16))[i] =
            make_float4(g16[4*i], g16[4*i+1], g16[4*i+2], g16[4*i+3]);
    }

    // load contributions
    float thr_in = topv[8], thr_out = topv[7];
    float ldv[16];
    #pragma unroll
    for (int e = 0; e < 16; e++) {
        bool in = nz[e] > thr_in;
        float thr = in ? thr_in : thr_out;
        float z = (cl[e] - thr) / sd[e];
        ldv[e] = 0.5f * (1.f + erff(z * 0.70710678118654752440f));
    }

    // warp reduce, then 16 global atomics per warp
    #pragma unroll
    for (int e = 0; e < 16; e++) {
        float v1 = g16[e], v2 = ldv[e];
        #pragma unroll
        for (int off = 16; off; off >>= 1) {
            v1 += __shfl_down_sync(0xffffffffu, v1, off);
            v2 += __shfl_down_sync(0xffffffffu, v2, off);
        }
        if (lane == 0) {
            atomicAdd(&g_importance[e], v1);
            atomicAdd(&g_load[e], v2);
        }
    }
}

// ---------------- kernel 3: loss -------------------------------------------
__global__ void k_loss(float* __restrict__ out)
{
    if (threadIdx.x == 0 && blockIdx.x == 0) {
        float mi = 0.f, ml = 0.f;
        for (int e = 0; e < En; e++) { mi += g_importance[e]; ml += g_load[e]; }
        mi *= (1.f / En); ml *= (1.f / En);
        float vi = 0.f, vl = 0.f;
        for (int e = 0; e < En; e++) {
            float d1 = g_importance[e] - mi; vi += d1 * d1;
            float d2 = g_load[e] - ml;       vl += d2 * d2;
        }
        vi /= (En - 1); vl /= (En - 1);
        float loss = 0.01f * (vi / (mi * mi + 1e-10f) + vl / (ml * ml + 1e-10f));
        out[(size_t)Bn * Hn] = loss;
    }
}

// ---------------- kernel 4: y = (G .* X) @ W' + G @ expert_b ---------------
// Single GEMM: M=8192, N=1024, K=16384 where A'[b, e*D+d] = gates[b,e]*x[b,d]
// and W' is expert_w flattened row-major (already contiguous).
#define BM 128
#define BN 128
#define BK 16
#define TM 8
#define TN 8
#define ASTRIDE (BM + 4)

__global__ __launch_bounds__(256) void k_moe_gemm(
    const float* __restrict__ x, const float* __restrict__ ew,
    const float* __restrict__ eb, float* __restrict__ out)
{
    __shared__ float As[2][BK][ASTRIDE];
    __shared__ float Bs[2][BK][BN];

    int tid  = threadIdx.x;
    int bRow = blockIdx.y * BM;
    int bCol = blockIdx.x * BN;

    int irA = tid >> 2;           // 0..63
    int icA = (tid & 3) << 2;     // 0,4,8,12
    int irB = tid >> 5;           // 0..7
    int icB = (tid & 31) << 2;    // 0..124
    int tR  = (tid >> 4) * TM;
    int tC  = (tid & 15) * TN;

    float acc[TM][TN];
    #pragma unroll
    for (int i = 0; i < TM; i++)
        #pragma unroll
        for (int j = 0; j < TN; j++) acc[i][j] = 0.f;

    float4 a0, a1, b0, b1;
    float ga0, ga1;
    const int NT = (En * Dn) / BK;   // 1024 k-tiles; each tile stays in one expert

#define FETCH(kt) do {                                                         \
        int e_  = (kt) >> 6;                                                   \
        int db_ = ((kt) & 63) * BK;                                            \
        const float* xr = x + (size_t)(bRow + irA) * Dn + db_ + icA;           \
        a0 = *(const float4*)xr;                                               \
        a1 = *(const float4*)(xr + (size_t)64 * Dn);                           \
        ga0 = g_gates[(size_t)(bRow + irA) * En + e_];                         \
        ga1 = g_gates[(size_t)(bRow + irA + 64) * En + e_];                    \
        const float* br = ew + (size_t)((kt) * BK + irB) * Hn + bCol + icB;    \
        b0 = *(const float4*)br;                                               \
        b1 = *(const float4*)(br + (size_t)8 * Hn);                            \
    } while (0)

#define STORE(bf) do {                                                         \
        As[bf][icA + 0][irA] = a0.x * ga0;                                     \
        As[bf][icA + 1][irA] = a0.y * ga0;                                     \
        As[bf][icA + 2][irA] = a0.z * ga0;                                     \
        As[bf][icA + 3][irA] = a0.w * ga0;                                     \
        As[bf][icA + 0][irA + 64] = a1.x * ga1;                                \
        As[bf][icA + 1][irA + 64] = a1.y * ga1;                                \
        As[bf][icA + 2][irA + 64] = a1.z * ga1;                                \
        As[bf][icA + 3][irA + 64] = a1.w * ga1;                                \
        *(float4*)&Bs[bf][irB][icB]     = b0;                                  \
        *(float4*)&Bs[bf][irB + 8][icB] = b1;                                  \
    } while (0)

    FETCH(0);
    STORE(0);
    __syncthreads();

    int buf = 0;
    for (int kt = 0; kt < NT; kt++) {
        if (kt + 1 < NT) FETCH(kt + 1);
        #pragma unroll
        for (int k = 0; k < BK; k++) {
            float ar[TM], brr[TN];
            *(float4*)&ar[0]  = *(const float4*)&As[buf][k][tR];
            *(float4*)&ar[4]  = *(const float4*)&As[buf][k][tR + 4];
            *(float4*)&brr[0] = *(const float4*)&Bs[buf][k][tC];
            *(float4*)&brr[4] = *(const float4*)&Bs[buf][k][tC + 4];
            #pragma unroll
            for (int i = 0; i < TM; i++)
                #pragma unroll
                for (int j = 0; j < TN; j++)
                    acc[i][j] = fmaf(ar[i], brr[j], acc[i][j]);
        }
        if (kt + 1 < NT) {
            STORE(buf ^ 1);
            __syncthreads();
            buf ^= 1;
        }
    }

    // --- epilogue: bias = gates @ expert_b, rank-16 update from smem -------
    __syncthreads();
    float* gts = &As[0][0][0];   // 128*16 floats
    float* ebs = &Bs[0][0][0];   // 16*128 floats
    for (int i = tid; i < (BM * En) / 4; i += 256)
        ((float4*)gts)[i] = ((const float4*)(g_gates + (size_t)bRow * En))[i];
    for (int i = tid; i < (En * BN) / 4; i += 256) {
        int e  = i / (BN / 4);
        int c4 = i % (BN / 4);
        ((float4*)ebs)[i] = *(const float4*)(eb + (size_t)e * Hn + bCol + c4 * 4);
    }
    __syncthreads();

    #pragma unroll
    for (int e = 0; e < En; e++) {
        float gr[TM], bb[TN];
        #pragma unroll
        for (int i = 0; i < TM; i++) gr[i] = gts[(tR + i) * En + e];
        #pragma unroll
        for (int j = 0; j < TN; j++) bb[j] = ebs[e * BN + tC + j];
        #pragma unroll
        for (int i = 0; i < TM; i++)
            #pragma unroll
            for (int j = 0; j < TN; j++)
                acc[i][j] = fmaf(gr[i], bb[j], acc[i][j]);
    }

    #pragma unroll
    for (int i = 0; i < TM; i++) {
        float* orow = out + (size_t)(bRow + tR + i) * Hn + bCol + tC;
        *(float4*)orow       = make_float4(acc[i][0], acc[i][1], acc[i][2], acc[i][3]);
        *(float4*)(orow + 4) = make_float4(acc[i][4], acc[i][5], acc[i][6], acc[i][7]);
    }
#undef FETCH
#undef STORE
}

// ---------------- launch ----------------------------------------------------
extern "C" void kernel_launch(void* const* d_in, const int* in_sizes, int n_in,
                              void* d_out, int out_size)
{
    const float* x     = (const float*)d_in[0];
    const float* wg    = (const float*)d_in[1];
    const float* wn    = (const float*)d_in[2];
    const float* ew    = (const float*)d_in[3];
    const float* eb    = (const float*)d_in[4];
    const float* noise = (const float*)d_in[5];
    float* out = (float*)d_out;

    k_init<<<1, 32>>>();
    k_logits<<<Bn, 1024>>>(x, wg, wn, noise);
    k_gate<<<Bn / 256, 256>>>();
    k_loss<<<1, 32>>>(out);
    dim3 grid(Hn / BN, Bn / BM);
    k_moe_gemm<<<grid, 256>>>(x, ew, eb, out);
}

// round 3
// speedup vs baseline: 6.2355x; 6.2355x over previous
#include <cuda_runtime.h>
#include <cuda_bf16.h>
#include <math.h>
#include <stdint.h>

#define Bn 8192
#define Dn 1024
#define En 16
#define Hn 1024

// ---------- arch-feature gate for tcgen05 (compiles away on base sm_103) ----
#if defined(__CUDA_ARCH__) && (defined(__CUDA_ARCH_FEAT_SM103_ALL) || defined(__CUDA_ARCH_FEAT_SM100_ALL) || defined(__CUDA_ARCH_FAMILY_SPECIFIC__))
#define HAS_TC 1
#else
#define HAS_TC 0
#endif

// ---------------- scratch ---------------------------------------------------
__device__ float g_clean[Bn * En];
__device__ float g_stddev[Bn * En];
__device__ float g_noisy[Bn * En];
__device__ float g_gates[Bn * En];
__device__ float g_importance[En];
__device__ float g_load[En];
__device__ int   g_tc;

// tcgen05-path scratch (unused when base compile; statically reserved)
#define TC_NCH 257
#define TC_ATILE 16384
#define TC_BTILE 32768
#define TC_STG (2*TC_ATILE + 2*TC_BTILE)
__device__ __align__(1024) unsigned char g_Ah[(size_t)64 * TC_NCH * TC_ATILE];
__device__ __align__(1024) unsigned char g_Al[(size_t)64 * TC_NCH * TC_ATILE];
__device__ __align__(1024) unsigned char g_Bh[(size_t)4  * TC_NCH * TC_BTILE];
__device__ __align__(1024) unsigned char g_Bl[(size_t)4  * TC_NCH * TC_BTILE];

#define SWZ(b) ((b) ^ (((b) >> 3) & 0x70))

// ---------------- generic PTX helpers (base-target legal) -------------------
__device__ __forceinline__ uint32_t smem_u32(const void* p) {
    uint32_t a;
    asm("{ .reg .u64 t; cvta.to.shared.u64 t, %1; cvt.u32.u64 %0, t; }" : "=r"(a) : "l"(p));
    return a;
}
#define MBAR_INIT(a, c) asm volatile("mbarrier.init.shared.b64 [%0], %1;" :: "r"(a), "r"((uint32_t)(c)) : "memory")
#define MBAR_EXPECT_TX(a, n) asm volatile("mbarrier.arrive.expect_tx.shared.b64 _, [%0], %1;" :: "r"(a), "r"((uint32_t)(n)) : "memory")
#define MBAR_WAIT(a, ph) do {                                                   \
    uint32_t _m = (a), _p = (ph), _d;                                           \
    asm volatile("{ .reg .pred p; mbarrier.try_wait.parity.acquire.cta.shared::cta.b64 p, [%1], %2; selp.b32 %0,1,0,p; }" \
        : "=r"(_d) : "r"(_m), "r"(_p) : "memory");                              \
    if (!_d) {                                                                  \
        asm volatile("{ .reg .pred P1; W%=: mbarrier.try_wait.parity.acquire.cta.shared::cta.b64 P1, [%0], %1, 0x989680; @P1 bra.uni D%=; bra.uni W%=; D%=: }" \
            :: "r"(_m), "r"(_p) : "memory");                                    \
    }                                                                           \
} while (0)

__device__ __forceinline__ void bulk_g2s(uint32_t dst, const void* src, uint32_t bytes, uint32_t mbar) {
    asm volatile("cp.async.bulk.shared::cluster.global.mbarrier::complete_tx::bytes [%0], [%1], %2, [%3];"
        :: "r"(dst), "l"(src), "r"(bytes), "r"(mbar) : "memory");
}
__device__ __forceinline__ void cpa16(uint32_t d, const void* s) {
    asm volatile("cp.async.cg.shared.global [%0], [%1], 16;" :: "r"(d), "l"(s) : "memory");
}
#define CPA_COMMIT() asm volatile("cp.async.commit_group;" ::: "memory")
#define CPA_WAIT2()  asm volatile("cp.async.wait_group 2;" ::: "memory")

__device__ __forceinline__ uint32_t f2tf(float v) {
    uint32_t r; asm("cvt.rna.tf32.f32 %0, %1;" : "=r"(r) : "f"(v)); return r;
}
__device__ __forceinline__ void mma_tf32(float* c, uint32_t a0, uint32_t a1, uint32_t a2, uint32_t a3,
                                         uint32_t b0, uint32_t b1) {
    asm volatile("mma.sync.aligned.m16n8k8.row.col.f32.tf32.tf32.f32 "
        "{%0,%1,%2,%3},{%4,%5,%6,%7},{%8,%9},{%0,%1,%2,%3};"
        : "+f"(c[0]), "+f"(c[1]), "+f"(c[2]), "+f"(c[3])
        : "r"(a0), "r"(a1), "r"(a2), "r"(a3), "r"(b0), "r"(b1));
}

union U8 { unsigned short s[8]; uint4 v; };
__device__ __forceinline__ void bsplit(float v, unsigned short& h, unsigned short& l) {
    __nv_bfloat16 hb = __float2bfloat16(v);
    h = __bfloat16_as_ushort(hb);
    l = __bfloat16_as_ushort(__float2bfloat16(v - __bfloat162float(hb)));
}

// ---------------- kernel 0: init ---------------------------------------------
__global__ void k_init() {
    int t = threadIdx.x;
    if (t < En) { g_importance[t] = 0.f; g_load[t] = 0.f; }
    if (t == 0) g_tc = HAS_TC;
}

// ---------------- kernel 1: gating logits (validated round-1 version) --------
__global__ __launch_bounds__(1024) void k_logits(
    const float* __restrict__ x, const float* __restrict__ wg,
    const float* __restrict__ wn, const float* __restrict__ noise)
{
    int b = blockIdx.x;
    __shared__ float xs[Dn];
    __shared__ float part[32];
    int tid = threadIdx.x;
    for (int i = tid; i < Dn; i += 1024) xs[i] = x[(size_t)b * Dn + i];
    __syncthreads();

    int w = tid >> 5, lane = tid & 31;
    int e = w & 15;
    const float* __restrict__ W = (w < 16) ? wg : wn;
    float s = 0.f;
    #pragma unroll
    for (int it = 0; it < Dn / 32; it++) {
        int i = lane + it * 32;
        s += xs[i] * W[i * En + e];
    }
    #pragma unroll
    for (int off = 16; off; off >>= 1) s += __shfl_down_sync(0xffffffffu, s, off);
    if (lane == 0) part[w] = s;
    __syncthreads();

    if (tid < 16) {
        float clean = part[tid];
        float raw   = part[tid + 16];
        float sp = fmaxf(raw, 0.f) + log1pf(expf(-fabsf(raw)));
        float sd = sp + 0.01f;
        float nz = clean + noise[b * En + tid] * sd;
        g_clean[b * En + tid]  = clean;
        g_stddev[b * En + tid] = sd;
        g_noisy[b * En + tid]  = nz;
    }
}

// ---------------- kernel 2: softmax / top-9 / gates / load -------------------
__global__ __launch_bounds__(256) void k_gate()
{
    int b = blockIdx.x * 256 + threadIdx.x;
    int lane = threadIdx.x & 31;

    float nz[16], cl[16], sd[16];
    #pragma unroll
    for (int i = 0; i < 4; i++) {
        float4 v = ((const float4*)(g_noisy  + (size_t)b * 16))[i];
        nz[4*i] = v.x; nz[4*i+1] = v.y; nz[4*i+2] = v.z; nz[4*i+3] = v.w;
        float4 c = ((const float4*)(g_clean  + (size_t)b * 16))[i];
        cl[4*i] = c.x; cl[4*i+1] = c.y; cl[4*i+2] = c.z; cl[4*i+3] = c.w;
        float4 s = ((const float4*)(g_stddev + (size_t)b * 16))[i];
        sd[4*i] = s.x; sd[4*i+1] = s.y; sd[4*i+2] = s.z; sd[4*i+3] = s.w;
    }

    float m = nz[0];
    #pragma unroll
    for (int e = 1; e < 16; e++) m = fmaxf(m, nz[e]);
    float p[16], sum = 0.f;
    #pragma unroll
    for (int e = 0; e < 16; e++) { p[e] = expf(nz[e] - m); sum += p[e]; }
    float inv = 1.f / sum;
    #pragma unroll
    for (int e = 0; e < 16; e++) p[e] *= inv;

    float topv[9]; int topi[9]; unsigned mask = 0;
    #pragma unroll
    for (int t = 0; t < 9; t++) {
        float best = -1.f; int bi = 0;
        #pragma unroll
        for (int e = 0; e < 16; e++) {
            bool ok = (!((mask >> e) & 1u)) && (p[e] > best);
            if (ok) { best = p[e]; bi = e; }
        }
        topv[t] = best; topi[t] = bi; mask |= (1u << bi);
    }

    float ksum = 0.f;
    #pragma unroll
    for (int t = 0; t < 8; t++) ksum += topv[t];
    float dinv = 1.f / (ksum + 1e-6f);

    float g16[16];
    #pragma unroll
    for (int e = 0; e < 16; e++) {
        float ge = 0.f;
        #pragma unroll
        for (int t = 0; t < 8; t++) ge = (topi[t] == e) ? topv[t] * dinv : ge;
        g16[e] = ge;
    }
    #pragma unroll
    for (int i = 0; i < 4; i++)
        ((float4*)(g_gates + (size_t)b * 16))[i] =
            make_float4(g16[4*i], g16[4*i+1], g16[4*i+2], g16[4*i+3]);

    float thr_in = topv[8], thr_out = topv[7];
    float ldv[16];
    #pragma unroll
    for (int e = 0; e < 16; e++) {
        bool in = nz[e] > thr_in;
        float thr = in ? thr_in : thr_out;
        float z = (cl[e] - thr) / sd[e];
        ldv[e] = 0.5f * (1.f + erff(z * 0.70710678118654752440f));
    }
    #pragma unroll
    for (int e = 0; e < 16; e++) {
        float v1 = g16[e], v2 = ldv[e];
        #pragma unroll
        for (int off = 16; off; off >>= 1) {
            v1 += __shfl_down_sync(0xffffffffu, v1, off);
            v2 += __shfl_down_sync(0xffffffffu, v2, off);
        }
        if (lane == 0) {
            atomicAdd(&g_importance[e], v1);
            atomicAdd(&g_load[e], v2);
        }
    }
}

// ---------------- kernel 3: loss ---------------------------------------------
__global__ void k_loss(float* __restrict__ out)
{
    if (threadIdx.x == 0 && blockIdx.x == 0) {
        float mi = 0.f, ml = 0.f;
        for (int e = 0; e < En; e++) { mi += g_importance[e]; ml += g_load[e]; }
        mi *= (1.f / En); ml *= (1.f / En);
        float vi = 0.f, vl = 0.f;
        for (int e = 0; e < En; e++) {
            float d1 = g_importance[e] - mi; vi += d1 * d1;
            float d2 = g_load[e] - ml;       vl += d2 * d2;
        }
        vi /= (En - 1); vl /= (En - 1);
        out[(size_t)Bn * Hn] = 0.01f * (vi / (mi * mi + 1e-10f) + vl / (ml * ml + 1e-10f));
    }
}

// =============================================================================
//  PATH A (guarded): tcgen05 bf16x3 GEMM — active only on 103a/family compiles
// =============================================================================
#define TC_MT 128
#define TC_NT 256

__global__ __launch_bounds__(256) void k_prep_a(const float* __restrict__ x)
{
#if HAS_TC
    int b = blockIdx.x;
    __shared__ float xs[1024];
    __shared__ float gs[16];
    int tid = threadIdx.x;
    ((float4*)xs)[tid] = ((const float4*)(x + (size_t)b * Dn))[tid];
    if (tid < 16) gs[tid] = g_gates[b * 16 + tid];
    __syncthreads();

    int mt = b >> 7, row = b & 127;
    size_t mbase = (size_t)mt * TC_NCH * TC_ATILE;

    #pragma unroll
    for (int it = 0; it < 8; it++) {
        int item = tid + it * 256;
        int e  = item >> 7;
        int d0 = (item & 127) * 8;
        float g = gs[e];
        U8 hi, lo;
        #pragma unroll
        for (int j = 0; j < 8; j++) bsplit(g * xs[d0 + j], hi.s[j], lo.s[j]);
        int kk  = e * 1024 + d0;
        int ch  = kk >> 6;
        int col = kk & 63;
        uint32_t off = SWZ((uint32_t)(row * 128 + col * 2));
        size_t addr = mbase + (size_t)ch * TC_ATILE + off;
        *(uint4*)(g_Ah + addr) = hi.v;
        *(uint4*)(g_Al + addr) = lo.v;
    }
    if (tid < 8) {
        U8 hi, lo;
        #pragma unroll
        for (int j = 0; j < 8; j++) {
            int c = tid * 8 + j;
            bsplit((c < 16) ? gs[c] : 0.f, hi.s[j], lo.s[j]);
        }
        size_t addr = mbase + (size_t)256 * TC_ATILE + SWZ((uint32_t)(row * 128 + tid * 16));
        *(uint4*)(g_Ah + addr) = hi.v;
        *(uint4*)(g_Al + addr) = lo.v;
    }
#endif
}

__global__ __launch_bounds__(256) void k_prep_b(const float* __restrict__ ew)
{
#if HAS_TC
    int h64 = blockIdx.x;
    int kc  = blockIdx.y;
    __shared__ float ts[64][65];
    int tid = threadIdx.x;
    int kl = tid >> 4;
    int h4 = (tid & 15) * 4;
    #pragma unroll
    for (int r = 0; r < 4; r++) {
        int kk = kl + r * 16;
        float4 v = *(const float4*)(ew + (size_t)(kc * 64 + kk) * Hn + h64 * 64 + h4);
        ts[h4 + 0][kk] = v.x; ts[h4 + 1][kk] = v.y;
        ts[h4 + 2][kk] = v.z; ts[h4 + 3][kk] = v.w;
    }
    __syncthreads();
    #pragma unroll
    for (int r2 = 0; r2 < 2; r2++) {
        int it = tid + r2 * 256;
        int hl = it >> 3, kg = it & 7;
        U8 hi, lo;
        #pragma unroll
        for (int j = 0; j < 8; j++) bsplit(ts[hl][kg * 8 + j], hi.s[j], lo.s[j]);
        int hg = h64 * 64 + hl;
        int ht = hg >> 8, rr = hg & 255;
        size_t addr = ((size_t)(ht * TC_NCH + kc)) * TC_BTILE + SWZ((uint32_t)(rr * 128 + kg * 16));
        *(uint4*)(g_Bh + addr) = hi.v;
        *(uint4*)(g_Bl + addr) = lo.v;
    }
#endif
}

__global__ __launch_bounds__(256) void k_prep_bb(const float* __restrict__ eb)
{
#if HAS_TC
    int ht = blockIdx.x;
    int row = threadIdx.x;
    int hg = ht * 256 + row;
    #pragma unroll
    for (int kg = 0; kg < 8; kg++) {
        U8 hi, lo;
        #pragma unroll
        for (int j = 0; j < 8; j++) {
            int c = kg * 8 + j;
            bsplit((c < 16) ? eb[c * Hn + hg] : 0.f, hi.s[j], lo.s[j]);
        }
        size_t addr = ((size_t)(ht * TC_NCH + 256)) * TC_BTILE + SWZ((uint32_t)(row * 128 + kg * 16));
        *(uint4*)(g_Bh + addr) = hi.v;
        *(uint4*)(g_Bl + addr) = lo.v;
    }
#endif
}

__global__ __launch_bounds__(128, 1) void k_gemm_tc(float* __restrict__ out)
{
#if HAS_TC
    extern __shared__ unsigned char smem[];
    uint32_t sb = smem_u32(smem);
    uint32_t tiles = (sb + 1024u) & ~1023u;
    uint32_t bfull0 = sb + 0,  bfull1 = sb + 8;
    uint32_t bemp0  = sb + 16, bemp1  = sb + 24;
    uint32_t bdone  = sb + 32;
    uint32_t tptr   = sb + 64;

    int tid = threadIdx.x, wid = tid >> 5, lane = tid & 31;
    int nt = blockIdx.x, mt = blockIdx.y;

    if (tid == 0) {
        MBAR_INIT(bfull0, 1); MBAR_INIT(bfull1, 1);
        MBAR_INIT(bemp0, 1);  MBAR_INIT(bemp1, 1);
        MBAR_INIT(bdone, 1);
    }
    __syncthreads();
    if (wid == 0) {
        asm volatile("tcgen05.alloc.cta_group::1.sync.aligned.shared::cta.b32 [%0], %1;" :: "r"(tptr), "r"((uint32_t)TC_NT) : "memory");
        asm volatile("tcgen05.relinquish_alloc_permit.cta_group::1.sync.aligned;");
    }
    __syncthreads();
    uint32_t tmem;
    asm volatile("ld.shared.b32 %0, [%1];" : "=r"(tmem) : "r"(tptr));

    const uint64_t DESC_BASE =
        (uint64_t(2) << 61) | (uint64_t(1) << 46) | (uint64_t(64) << 32) | (uint64_t(1) << 16);
    const uint32_t GIDESC = (1u<<4) | (1u<<7) | (1u<<10) | ((TC_NT/8u)<<17) | ((TC_MT/16u)<<24);

    if (tid == 0) {
        const unsigned char* pAh = g_Ah + (size_t)mt * TC_NCH * TC_ATILE;
        const unsigned char* pAl = g_Al + (size_t)mt * TC_NCH * TC_ATILE;
        const unsigned char* pBh = g_Bh + (size_t)nt * TC_NCH * TC_BTILE;
        const unsigned char* pBl = g_Bl + (size_t)nt * TC_NCH * TC_BTILE;
        uint32_t eph[2] = {0, 0};
        for (int c = 0; c < TC_NCH; c++) {
            int s = c & 1;
            uint32_t bemp = s ? bemp1 : bemp0;
            uint32_t bful = s ? bfull1 : bfull0;
            if (c >= 2) { MBAR_WAIT(bemp, eph[s]); eph[s] ^= 1; }
            uint32_t st = tiles + s * TC_STG;
            MBAR_EXPECT_TX(bful, TC_STG);
            bulk_g2s(st,                       pAh + (size_t)c * TC_ATILE, TC_ATILE, bful);
            bulk_g2s(st + TC_ATILE,            pAl + (size_t)c * TC_ATILE, TC_ATILE, bful);
            bulk_g2s(st + 2 * TC_ATILE,        pBh + (size_t)c * TC_BTILE, TC_BTILE, bful);
            bulk_g2s(st + 2*TC_ATILE+TC_BTILE, pBl + (size_t)c * TC_BTILE, TC_BTILE, bful);
        }
    } else if (tid == 32) {
        uint32_t fph[2] = {0, 0};
        uint32_t acc = 0;
        for (int c = 0; c < TC_NCH; c++) {
            int s = c & 1;
            uint32_t bful = s ? bfull1 : bfull0;
            uint32_t bemp = s ? bemp1 : bemp0;
            MBAR_WAIT(bful, fph[s]); fph[s] ^= 1;
            uint32_t st = tiles + s * TC_STG;
            uint64_t dah = DESC_BASE | ((uint64_t)(st >> 4) & 0x3FFF);
            uint64_t dal = DESC_BASE | ((uint64_t)((st + TC_ATILE) >> 4) & 0x3FFF);
            uint64_t dbh = DESC_BASE | ((uint64_t)((st + 2*TC_ATILE) >> 4) & 0x3FFF);
            uint64_t dbl = DESC_BASE | ((uint64_t)((st + 2*TC_ATILE + TC_BTILE) >> 4) & 0x3FFF);
            #pragma unroll
            for (int ks = 0; ks < 4; ks++) {
                asm volatile("{ .reg .pred p; setp.ne.u32 p, %5, 0;\n"
                    "tcgen05.mma.cta_group::1.kind::f16 [%0], %1, %2, %3, {%4,%4,%4,%4}, p; }"
                    :: "r"(tmem), "l"(dah + ks*2), "l"(dbh + ks*2), "r"(GIDESC), "r"(0u), "r"(acc) : "memory");
                acc = 1;
                asm volatile("{ .reg .pred p; setp.ne.u32 p, %5, 0;\n"
                    "tcgen05.mma.cta_group::1.kind::f16 [%0], %1, %2, %3, {%4,%4,%4,%4}, p; }"
                    :: "r"(tmem), "l"(dal + ks*2), "l"(dbh + ks*2), "r"(GIDESC), "r"(0u), "r"(1u) : "memory");
                asm volatile("{ .reg .pred p; setp.ne.u32 p, %5, 0;\n"
                    "tcgen05.mma.cta_group::1.kind::f16 [%0], %1, %2, %3, {%4,%4,%4,%4}, p; }"
                    :: "r"(tmem), "l"(dah + ks*2), "l"(dbl + ks*2), "r"(GIDESC), "r"(0u), "r"(1u) : "memory");
            }
            asm volatile("tcgen05.commit.cta_group::1.mbarrier::arrive::one.shared::cluster.b64 [%0];" :: "r"(bemp) : "memory");
        }
        asm volatile("tcgen05.commit.cta_group::1.mbarrier::arrive::one.shared::cluster.b64 [%0];" :: "r"(bdone) : "memory");
    }

    MBAR_WAIT(bdone, 0);
    asm volatile("tcgen05.fence::after_thread_sync;" ::: "memory");

    int row = mt * TC_MT + wid * 32 + lane;
    float* orow = out + (size_t)row * Hn + nt * TC_NT;
    #pragma unroll
    for (int cc = 0; cc < 8; cc++) {
        uint32_t r[32];
        asm volatile(
            "tcgen05.ld.sync.aligned.32x32b.x32.b32 "
            "{%0,%1,%2,%3,%4,%5,%6,%7,%8,%9,%10,%11,%12,%13,%14,%15,"
            "%16,%17,%18,%19,%20,%21,%22,%23,%24,%25,%26,%27,%28,%29,%30,%31}, [%32];"
            : "=r"(r[0]),"=r"(r[1]),"=r"(r[2]),"=r"(r[3]),"=r"(r[4]),"=r"(r[5]),"=r"(r[6]),"=r"(r[7]),
              "=r"(r[8]),"=r"(r[9]),"=r"(r[10]),"=r"(r[11]),"=r"(r[12]),"=r"(r[13]),"=r"(r[14]),"=r"(r[15]),
              "=r"(r[16]),"=r"(r[17]),"=r"(r[18]),"=r"(r[19]),"=r"(r[20]),"=r"(r[21]),"=r"(r[22]),"=r"(r[23]),
              "=r"(r[24]),"=r"(r[25]),"=r"(r[26]),"=r"(r[27]),"=r"(r[28]),"=r"(r[29]),"=r"(r[30]),"=r"(r[31])
            : "r"(tmem + cc * 32));
        asm volatile("tcgen05.wait::ld.sync.aligned;" ::: "memory");
        #pragma unroll
        for (int q = 0; q < 8; q++) {
            *(float4*)(orow + cc * 32 + q * 4) = make_float4(
                __uint_as_float(r[q*4+0]), __uint_as_float(r[q*4+1]),
                __uint_as_float(r[q*4+2]), __uint_as_float(r[q*4+3]));
        }
    }
    __syncthreads();
    if (wid == 0)
        asm volatile("tcgen05.dealloc.cta_group::1.sync.aligned.b32 %0, %1;" :: "r"(tmem), "r"((uint32_t)TC_NT));
#endif
}

// =============================================================================
//  PATH B: tf32 mma.sync GEMM (base-target legal) — the expected runner
//  y[b,h] = sum_k (g[b,e(k)]*x[b,d(k)]) * ew[k,h]  + sum_e g[b,e]*eb[e,h]
// =============================================================================
#define BM 128
#define BN 128
#define BK 32
#define STAGES 4
#define ASTR 44      // floats per A row  (stride%32 = 12 -> conflict-free frags)
#define BSTR 136     // floats per B row  (stride%32 = 8  -> conflict-free frags)
#define GSTR 17
#define A_ST_FLT (BM * ASTR)          // 5632
#define B_ST_FLT (BK * BSTR)          // 4352
#define NTILES (En * Dn / BK)         // 512

__global__ __launch_bounds__(256, 1) void k_gemm_mma(
    const float* __restrict__ x, const float* __restrict__ ew,
    const float* __restrict__ eb, float* __restrict__ out)
{
    if (g_tc) return;

    extern __shared__ float sm[];
    float* As  = sm;                          // [4][128][44]
    float* Bs  = sm + STAGES * A_ST_FLT;      // [4][32][136]
    float* gs  = Bs + STAGES * B_ST_FLT;      // [128][17]
    float* ebs = gs + BM * GSTR;              // [16][128]

    const int tid  = threadIdx.x;
    const int lane = tid & 31;
    const int wid  = tid >> 5;
    const int wm   = wid >> 2;                // 0..1
    const int wn   = wid & 3;                 // 0..3
    const int grp  = lane >> 2;
    const int qid  = lane & 3;
    const int bM = blockIdx.y * BM;
    const int bN = blockIdx.x * BN;

    // gates + bias tiles
    for (int i = tid; i < BM * En; i += 256) {
        int r = i >> 4, e = i & 15;
        gs[r * GSTR + e] = g_gates[(size_t)(bM + r) * En + e];
    }
    for (int i = tid; i < En * BN; i += 256) {
        int e = i >> 7, c = i & 127;
        ebs[e * BN + c] = eb[(size_t)e * Hn + bN + c];
    }

    // cp.async source/dest precompute
    const uint32_t sbase = smem_u32(sm);
    const int ar = tid >> 1, ac = (tid & 1) * 4;          // A: 1 chunk / thread
    const int bk0 = tid >> 5, bc0 = (tid & 31) * 4;       // B: 4 chunks / thread
    const uint32_t adst0 = sbase + (uint32_t)(ar * ASTR + ac) * 4u;
    const uint32_t bdst0 = sbase + (uint32_t)(STAGES * A_ST_FLT + bk0 * BSTR + bc0) * 4u;

#define LOAD_TILE(kt, s) do {                                                   \
        int _d0 = ((kt) * BK) & (Dn - 1);                                       \
        cpa16(adst0 + (uint32_t)((s) * A_ST_FLT * 4),                           \
              x + (size_t)(bM + ar) * Dn + _d0 + ac);                           \
        const float* _bw = ew + (size_t)((kt) * BK + bk0) * Hn + bN + bc0;      \
        uint32_t _bd = bdst0 + (uint32_t)((s) * B_ST_FLT * 4);                  \
        cpa16(_bd,                      _bw);                                   \
        cpa16(_bd + 8u*BSTR*4u,         _bw + (size_t)8  * Hn);                 \
        cpa16(_bd + 16u*BSTR*4u,        _bw + (size_t)16 * Hn);                 \
        cpa16(_bd + 24u*BSTR*4u,        _bw + (size_t)24 * Hn);                 \
    } while (0)

    #pragma unroll
    for (int s = 0; s < STAGES - 1; s++) { LOAD_TILE(s, s); CPA_COMMIT(); }

    float acc[4][4][4];
    #pragma unroll
    for (int mi = 0; mi < 4; mi++)
        #pragma unroll
        for (int ni = 0; ni < 4; ni++)
            #pragma unroll
            for (int q = 0; q < 4; q++) acc[mi][ni][q] = 0.f;

    // per-lane fragment bases (element offsets within a stage)
    const int aoff = (wm * 64 + grp) * ASTR + qid;
    const int boff = qid * BSTR + wn * 32 + grp;

    float g0[4], g1[4];
    __syncthreads();   // gs/ebs ready

    for (int kt = 0; kt < NTILES; kt++) {
        CPA_WAIT2();
        __syncthreads();

        if ((kt & 31) == 0) {
            int e = kt >> 5;
            #pragma unroll
            for (int mi = 0; mi < 4; mi++) {
                g0[mi] = gs[(wm * 64 + mi * 16 + grp) * GSTR + e];
                g1[mi] = gs[(wm * 64 + mi * 16 + grp + 8) * GSTR + e];
            }
        }

        int nk = kt + STAGES - 1;
        if (nk < NTILES) LOAD_TILE(nk, nk & (STAGES - 1));
        CPA_COMMIT();

        const float* Ap = As + (kt & (STAGES - 1)) * A_ST_FLT + aoff;
        const float* Bp = Bs + (kt & (STAGES - 1)) * B_ST_FLT + boff;

        #pragma unroll
        for (int ks = 0; ks < 4; ks++) {
            uint32_t bf[4][2];
            #pragma unroll
            for (int ni = 0; ni < 4; ni++) {
                bf[ni][0] = f2tf(Bp[(ks * 8) * BSTR + ni * 8]);
                bf[ni][1] = f2tf(Bp[(ks * 8 + 4) * BSTR + ni * 8]);
            }
            #pragma unroll
            for (int mi = 0; mi < 4; mi++) {
                const float* ab = Ap + mi * 16 * ASTR + ks * 8;
                uint32_t a0 = f2tf(g0[mi] * ab[0]);
                uint32_t a1 = f2tf(g1[mi] * ab[8 * ASTR]);
                uint32_t a2 = f2tf(g0[mi] * ab[4]);
                uint32_t a3 = f2tf(g1[mi] * ab[8 * ASTR + 4]);
                #pragma unroll
                for (int ni = 0; ni < 4; ni++)
                    mma_tf32(acc[mi][ni], a0, a1, a2, a3, bf[ni][0], bf[ni][1]);
            }
        }
    }

    // ---- epilogue: bias (rank-16) + stores ----------------------------------
    #pragma unroll
    for (int mi = 0; mi < 4; mi++) {
        int r0 = wm * 64 + mi * 16 + grp;
        #pragma unroll
        for (int e = 0; e < En; e++) {
            float ge0 = gs[r0 * GSTR + e];
            float ge1 = gs[(r0 + 8) * GSTR + e];
            #pragma unroll
            for (int ni = 0; ni < 4; ni++) {
                int c0 = wn * 32 + ni * 8 + 2 * qid;
                float b0v = ebs[e * BN + c0];
                float b1v = ebs[e * BN + c0 + 1];
                acc[mi][ni][0] = fmaf(ge0, b0v, acc[mi][ni][0]);
                acc[mi][ni][1] = fmaf(ge0, b1v, acc[mi][ni][1]);
                acc[mi][ni][2] = fmaf(ge1, b0v, acc[mi][ni][2]);
                acc[mi][ni][3] = fmaf(ge1, b1v, acc[mi][ni][3]);
            }
        }
    }

    #pragma unroll
    for (int mi = 0; mi < 4; mi++) {
        int r0 = bM + wm * 64 + mi * 16 + grp;
        #pragma unroll
        for (int ni = 0; ni < 4; ni++) {
            int c0 = bN + wn * 32 + ni * 8 + 2 * qid;
            *(float2*)(out + (size_t)r0 * Hn + c0)       = make_float2(acc[mi][ni][0], acc[mi][ni][1]);
            *(float2*)(out + (size_t)(r0 + 8) * Hn + c0) = make_float2(acc[mi][ni][2], acc[mi][ni][3]);
        }
    }
#undef LOAD_TILE
}

// ---------------- launch ------------------------------------------------------
extern "C" void kernel_launch(void* const* d_in, const int* in_sizes, int n_in,
                              void* d_out, int out_size)
{
    const float* x     = (const float*)d_in[0];
    const float* wg    = (const float*)d_in[1];
    const float* wn    = (const float*)d_in[2];
    const float* ew    = (const float*)d_in[3];
    const float* eb    = (const float*)d_in[4];
    const float* noise = (const float*)d_in[5];
    float* out = (float*)d_out;

    static const int TC_SMEM  = 1024 + 2 * TC_STG;
    static const int MMA_SMEM = (STAGES * (A_ST_FLT + B_ST_FLT) + BM * GSTR + En * BN) * 4;
    cudaFuncSetAttribute(k_gemm_tc,  cudaFuncAttributeMaxDynamicSharedMemorySize, TC_SMEM);
    cudaFuncSetAttribute(k_gemm_mma, cudaFuncAttributeMaxDynamicSharedMemorySize, MMA_SMEM);

    k_init<<<1, 32>>>();
    k_logits<<<Bn, 1024>>>(x, wg, wn, noise);
    k_gate<<<Bn / 256, 256>>>();
    k_loss<<<1, 32>>>(out);

    // tcgen05 path (no-ops when compiled for base sm_103)
    k_prep_a<<<Bn, 256>>>(x);
    k_prep_b<<<dim3(16, 256), 256>>>(ew);
    k_prep_bb<<<4, 256>>>(eb);
    k_gemm_tc<<<dim3(Hn / TC_NT, Bn / TC_MT), 128, TC_SMEM>>>(out);

    // mma.sync fallback (early-exits if tc path is live)
    k_gemm_mma<<<dim3(Hn / BN, Bn / BM), 256, MMA_SMEM>>>(x, ew, eb, out);
}

// round 4
// speedup vs baseline: 6.7508x; 1.0826x over previous
#include <cuda_runtime.h>
#include <cuda_bf16.h>
#include <math.h>
#include <stdint.h>

#define Bn 8192
#define Dn 1024
#define En 16
#define Hn 1024

// ---------- arch-feature gate for tcgen05 (compiles away on base sm_103) ----
#if defined(__CUDA_ARCH__) && (defined(__CUDA_ARCH_FEAT_SM103_ALL) || defined(__CUDA_ARCH_FEAT_SM100_ALL) || defined(__CUDA_ARCH_FAMILY_SPECIFIC__))
#define HAS_TC 1
#else
#define HAS_TC 0
#endif

// ---------------- scratch ---------------------------------------------------
__device__ float g_clean[Bn * En];
__device__ float g_stddev[Bn * En];
__device__ float g_noisy[Bn * En];
__device__ float g_gates[Bn * En];
__device__ float g_importance[En];
__device__ float g_load[En];
__device__ int   g_tc;

// B operand scratch: pre-split bf16 hi/lo, tiled (4 nt-tiles x 257 chunks),
// each chunk 256 rows x 64 cols bf16 = 32KB, SW128 swizzled.
#define TC_NCH 257
#define TC_BTILE 32768
__device__ __align__(1024) unsigned char g_Bh[(size_t)4 * TC_NCH * TC_BTILE];
__device__ __align__(1024) unsigned char g_Bl[(size_t)4 * TC_NCH * TC_BTILE];

#define SWZ(b) ((b) ^ (((b) >> 3) & 0x70))

// ---------------- generic PTX helpers (base-target legal) -------------------
__device__ __forceinline__ uint32_t smem_u32(const void* p) {
    uint32_t a;
    asm("{ .reg .u64 t; cvta.to.shared.u64 t, %1; cvt.u32.u64 %0, t; }" : "=r"(a) : "l"(p));
    return a;
}
#define MBAR_INIT(a, c) asm volatile("mbarrier.init.shared.b64 [%0], %1;" :: "r"(a), "r"((uint32_t)(c)) : "memory")
#define MBAR_EXPECT_TX(a, n) asm volatile("mbarrier.arrive.expect_tx.shared.b64 _, [%0], %1;" :: "r"(a), "r"((uint32_t)(n)) : "memory")
#define MBAR_ARRIVE(a) asm volatile("mbarrier.arrive.shared.b64 _, [%0];" :: "r"(a) : "memory")
#define MBAR_WAIT(a, ph) do {                                                   \
    uint32_t _m = (a), _p = (ph), _d;                                           \
    asm volatile("{ .reg .pred p; mbarrier.try_wait.parity.acquire.cta.shared::cta.b64 p, [%1], %2; selp.b32 %0,1,0,p; }" \
        : "=r"(_d) : "r"(_m), "r"(_p) : "memory");                              \
    if (!_d) {                                                                  \
        asm volatile("{ .reg .pred P1; W%=: mbarrier.try_wait.parity.acquire.cta.shared::cta.b64 P1, [%0], %1, 0x989680; @P1 bra.uni D%=; bra.uni W%=; D%=: }" \
            :: "r"(_m), "r"(_p) : "memory");                                    \
    }                                                                           \
} while (0)

__device__ __forceinline__ void bulk_g2s(uint32_t dst, const void* src, uint32_t bytes, uint32_t mbar) {
    asm volatile("cp.async.bulk.shared::cluster.global.mbarrier::complete_tx::bytes [%0], [%1], %2, [%3];"
        :: "r"(dst), "l"(src), "r"(bytes), "r"(mbar) : "memory");
}
__device__ __forceinline__ void cpa16(uint32_t d, const void* s) {
    asm volatile("cp.async.cg.shared.global [%0], [%1], 16;" :: "r"(d), "l"(s) : "memory");
}
#define CPA_COMMIT() asm volatile("cp.async.commit_group;" ::: "memory")
#define CPA_WAIT2()  asm volatile("cp.async.wait_group 2;" ::: "memory")

__device__ __forceinline__ uint32_t f2tf(float v) {
    uint32_t r; asm("cvt.rna.tf32.f32 %0, %1;" : "=r"(r) : "f"(v)); return r;
}
__device__ __forceinline__ void mma_tf32(float* c, uint32_t a0, uint32_t a1, uint32_t a2, uint32_t a3,
                                         uint32_t b0, uint32_t b1) {
    asm volatile("mma.sync.aligned.m16n8k8.row.col.f32.tf32.tf32.f32 "
        "{%0,%1,%2,%3},{%4,%5,%6,%7},{%8,%9},{%0,%1,%2,%3};"
        : "+f"(c[0]), "+f"(c[1]), "+f"(c[2]), "+f"(c[3])
        : "r"(a0), "r"(a1), "r"(a2), "r"(a3), "r"(b0), "r"(b1));
}

union U8 { unsigned short s[8]; uint4 v; };
__device__ __forceinline__ void bsplit(float v, unsigned short& h, unsigned short& l) {
    __nv_bfloat16 hb = __float2bfloat16(v);
    h = __bfloat16_as_ushort(hb);
    l = __bfloat16_as_ushort(__float2bfloat16(v - __bfloat162float(hb)));
}
// pair split -> packed bf16x2 words (low half = first element)
__device__ __forceinline__ void bsplit2(float v0, float v1, uint32_t& hw, uint32_t& lw) {
    __nv_bfloat16 h0 = __float2bfloat16(v0);
    __nv_bfloat16 h1 = __float2bfloat16(v1);
    float r0 = v0 - __bfloat162float(h0);
    float r1 = v1 - __bfloat162float(h1);
    __nv_bfloat162 hp = __halves2bfloat162(h0, h1);
    __nv_bfloat162 lp = __halves2bfloat162(__float2bfloat16(r0), __float2bfloat16(r1));
    hw = *(uint32_t*)&hp;
    lw = *(uint32_t*)&lp;
}

// ---------------- kernel 0: init ---------------------------------------------
__global__ void k_init() {
    int t = threadIdx.x;
    if (t < En) { g_importance[t] = 0.f; g_load[t] = 0.f; }
    if (t == 0) g_tc = HAS_TC;
}

// ---------------- kernel 1: gating logits -------------------------------------
__global__ __launch_bounds__(1024) void k_logits(
    const float* __restrict__ x, const float* __restrict__ wg,
    const float* __restrict__ wn, const float* __restrict__ noise)
{
    int b = blockIdx.x;
    __shared__ float xs[Dn];
    __shared__ float part[32];
    int tid = threadIdx.x;
    for (int i = tid; i < Dn; i += 1024) xs[i] = x[(size_t)b * Dn + i];
    __syncthreads();

    int w = tid >> 5, lane = tid & 31;
    int e = w & 15;
    const float* __restrict__ W = (w < 16) ? wg : wn;
    float s = 0.f;
    #pragma unroll
    for (int it = 0; it < Dn / 32; it++) {
        int i = lane + it * 32;
        s += xs[i] * W[i * En + e];
    }
    #pragma unroll
    for (int off = 16; off; off >>= 1) s += __shfl_down_sync(0xffffffffu, s, off);
    if (lane == 0) part[w] = s;
    __syncthreads();

    if (tid < 16) {
        float clean = part[tid];
        float raw   = part[tid + 16];
        float sp = fmaxf(raw, 0.f) + log1pf(expf(-fabsf(raw)));
        float sd = sp + 0.01f;
        float nz = clean + noise[b * En + tid] * sd;
        g_clean[b * En + tid]  = clean;
        g_stddev[b * En + tid] = sd;
        g_noisy[b * En + tid]  = nz;
    }
}

// ---------------- kernel 2: softmax / top-9 / gates / load -------------------
__global__ __launch_bounds__(256) void k_gate()
{
    int b = blockIdx.x * 256 + threadIdx.x;
    int lane = threadIdx.x & 31;

    float nz[16], cl[16], sd[16];
    #pragma unroll
    for (int i = 0; i < 4; i++) {
        float4 v = ((const float4*)(g_noisy  + (size_t)b * 16))[i];
        nz[4*i] = v.x; nz[4*i+1] = v.y; nz[4*i+2] = v.z; nz[4*i+3] = v.w;
        float4 c = ((const float4*)(g_clean  + (size_t)b * 16))[i];
        cl[4*i] = c.x; cl[4*i+1] = c.y; cl[4*i+2] = c.z; cl[4*i+3] = c.w;
        float4 s = ((const float4*)(g_stddev + (size_t)b * 16))[i];
        sd[4*i] = s.x; sd[4*i+1] = s.y; sd[4*i+2] = s.z; sd[4*i+3] = s.w;
    }

    float m = nz[0];
    #pragma unroll
    for (int e = 1; e < 16; e++) m = fmaxf(m, nz[e]);
    float p[16], sum = 0.f;
    #pragma unroll
    for (int e = 0; e < 16; e++) { p[e] = expf(nz[e] - m); sum += p[e]; }
    float inv = 1.f / sum;
    #pragma unroll
    for (int e = 0; e < 16; e++) p[e] *= inv;

    float topv[9]; int topi[9]; unsigned mask = 0;
    #pragma unroll
    for (int t = 0; t < 9; t++) {
        float best = -1.f; int bi = 0;
        #pragma unroll
        for (int e = 0; e < 16; e++) {
            bool ok = (!((mask >> e) & 1u)) && (p[e] > best);
            if (ok) { best = p[e]; bi = e; }
        }
        topv[t] = best; topi[t] = bi; mask |= (1u << bi);
    }

    float ksum = 0.f;
    #pragma unroll
    for (int t = 0; t < 8; t++) ksum += topv[t];
    float dinv = 1.f / (ksum + 1e-6f);

    float g16[16];
    #pragma unroll
    for (int e = 0; e < 16; e++) {
        float ge = 0.f;
        #pragma unroll
        for (int t = 0; t < 8; t++) ge = (topi[t] == e) ? topv[t] * dinv : ge;
        g16[e] = ge;
    }
    #pragma unroll
    for (int i = 0; i < 4; i++)
        ((float4*)(g_gates + (size_t)b * 16))[i] =
            make_float4(g16[4*i], g16[4*i+1], g16[4*i+2], g16[4*i+3]);

    float thr_in = topv[8], thr_out = topv[7];
    float ldv[16];
    #pragma unroll
    for (int e = 0; e < 16; e++) {
        bool in = nz[e] > thr_in;
        float thr = in ? thr_in : thr_out;
        float z = (cl[e] - thr) / sd[e];
        ldv[e] = 0.5f * (1.f + erff(z * 0.70710678118654752440f));
    }
    #pragma unroll
    for (int e = 0; e < 16; e++) {
        float v1 = g16[e], v2 = ldv[e];
        #pragma unroll
        for (int off = 16; off; off >>= 1) {
            v1 += __shfl_down_sync(0xffffffffu, v1, off);
            v2 += __shfl_down_sync(0xffffffffu, v2, off);
        }
        if (lane == 0) {
            atomicAdd(&g_importance[e], v1);
            atomicAdd(&g_load[e], v2);
        }
    }
}

// ---------------- kernel 3: loss ---------------------------------------------
__global__ void k_loss(float* __restrict__ out)
{
    if (threadIdx.x == 0 && blockIdx.x == 0) {
        float mi = 0.f, ml = 0.f;
        for (int e = 0; e < En; e++) { mi += g_importance[e]; ml += g_load[e]; }
        mi *= (1.f / En); ml *= (1.f / En);
        float vi = 0.f, vl = 0.f;
        for (int e = 0; e < En; e++) {
            float d1 = g_importance[e] - mi; vi += d1 * d1;
            float d2 = g_load[e] - ml;       vl += d2 * d2;
        }
        vi /= (En - 1); vl /= (En - 1);
        out[(size_t)Bn * Hn] = 0.01f * (vi / (mi * mi + 1e-10f) + vl / (ml * ml + 1e-10f));
    }
}

// ---------------- kernel 5: B = expert_w split+tiled+swizzled (tc path) ------
__global__ __launch_bounds__(256) void k_prep_b(const float* __restrict__ ew)
{
#if HAS_TC
    int h64 = blockIdx.x;
    int kc  = blockIdx.y;
    __shared__ float ts[64][65];
    int tid = threadIdx.x;
    int kl = tid >> 4;
    int h4 = (tid & 15) * 4;
    #pragma unroll
    for (int r = 0; r < 4; r++) {
        int kk = kl + r * 16;
        float4 v = *(const float4*)(ew + (size_t)(kc * 64 + kk) * Hn + h64 * 64 + h4);
        ts[h4 + 0][kk] = v.x; ts[h4 + 1][kk] = v.y;
        ts[h4 + 2][kk] = v.z; ts[h4 + 3][kk] = v.w;
    }
    __syncthreads();
    #pragma unroll
    for (int r2 = 0; r2 < 2; r2++) {
        int it = tid + r2 * 256;
        int hl = it >> 3, kg = it & 7;
        U8 hi, lo;
        #pragma unroll
        for (int j = 0; j < 8; j++) bsplit(ts[hl][kg * 8 + j], hi.s[j], lo.s[j]);
        int hg = h64 * 64 + hl;
        int ht = hg >> 8, rr = hg & 255;
        size_t addr = ((size_t)(ht * TC_NCH + kc)) * TC_BTILE + SWZ((uint32_t)(rr * 128 + kg * 16));
        *(uint4*)(g_Bh + addr) = hi.v;
        *(uint4*)(g_Bl + addr) = lo.v;
    }
#endif
}

__global__ __launch_bounds__(256) void k_prep_bb(const float* __restrict__ eb)
{
#if HAS_TC
    int ht = blockIdx.x;
    int row = threadIdx.x;
    int hg = ht * 256 + row;
    #pragma unroll
    for (int kg = 0; kg < 8; kg++) {
        U8 hi, lo;
        #pragma unroll
        for (int j = 0; j < 8; j++) {
            int c = kg * 8 + j;
            bsplit((c < 16) ? eb[c * Hn + hg] : 0.f, hi.s[j], lo.s[j]);
        }
        size_t addr = ((size_t)(ht * TC_NCH + 256)) * TC_BTILE + SWZ((uint32_t)(row * 128 + kg * 16));
        *(uint4*)(g_Bh + addr) = hi.v;
        *(uint4*)(g_Bl + addr) = lo.v;
    }
#endif
}

// =============================================================================
//  kernel 7 (tc path): fused GEMM — A split computed in-kernel from x + gates
//  M tile 128, N tile 256, chunk K=64, 257 chunks (last = bias rank-16).
//  warps 0-7: A converters; warp 8 lane0: B producer; warp 9 lane0: MMA issuer.
// =============================================================================
#define TC_MT 128
#define TC_NT 256
// SMEM layout (dynamic, byte offsets):
//   0     : barriers (a_full[2]@0,8  b_full[2]@16,24  done[2]@32,40  bdone@48  tptr@64)
//   1024  : Ah0(16K) Al0(16K) Ah1 Al1               -> 1024 .. 66560
//   66560 : Bh0(32K) Bl0 Bh1 Bl1                    -> 66560 .. 197632
//   197632: gates float[128*17]                     -> 206336
#define SM_A(s)   (1024u + (uint32_t)(s) * 32768u)
#define SM_AL(s)  (SM_A(s) + 16384u)
#define SM_B(s)   (66560u + (uint32_t)(s) * 65536u)
#define SM_BL(s)  (SM_B(s) + 32768u)
#define SM_GS     197632u
#define GEMM2_SMEM 206848

__global__ __launch_bounds__(320, 1) void k_gemm_tc2(const float* __restrict__ x,
                                                     float* __restrict__ out)
{
#if HAS_TC
    extern __shared__ unsigned char smc[];
    const uint32_t sb = smem_u32(smc);
    const uint32_t mb_af0 = sb + 0,  mb_af1 = sb + 8;
    const uint32_t mb_bf0 = sb + 16, mb_bf1 = sb + 24;
    const uint32_t mb_dn0 = sb + 32, mb_dn1 = sb + 40;
    const uint32_t mb_done = sb + 48;
    const uint32_t tptr    = sb + 64;
    float* gs = (float*)(smc + SM_GS);

    const int tid = threadIdx.x, wid = tid >> 5, lane = tid & 31;
    const int nt = blockIdx.x, mt = blockIdx.y;
    const int bM = mt * TC_MT;

    if (tid == 0) {
        MBAR_INIT(mb_af0, 256); MBAR_INIT(mb_af1, 256);
        MBAR_INIT(mb_bf0, 1);   MBAR_INIT(mb_bf1, 1);
        MBAR_INIT(mb_dn0, 1);   MBAR_INIT(mb_dn1, 1);
        MBAR_INIT(mb_done, 1);
    }
    // gates tile -> smem
    for (int i = tid; i < TC_MT * En; i += 320) {
        int r = i >> 4, e = i & 15;
        gs[r * 17 + e] = g_gates[(size_t)(bM + r) * En + e];
    }
    __syncthreads();
    if (wid == 9) {
        asm volatile("tcgen05.alloc.cta_group::1.sync.aligned.shared::cta.b32 [%0], %1;" :: "r"(tptr), "r"((uint32_t)TC_NT) : "memory");
        asm volatile("tcgen05.relinquish_alloc_permit.cta_group::1.sync.aligned;");
    }
    __syncthreads();
    uint32_t tmem;
    asm volatile("ld.shared.b32 %0, [%1];" : "=r"(tmem) : "r"(tptr));

    const uint64_t DESC_BASE =
        (uint64_t(2) << 61) | (uint64_t(1) << 46) | (uint64_t(64) << 32) | (uint64_t(1) << 16);
    const uint32_t GIDESC = (1u<<4) | (1u<<7) | (1u<<10) | ((TC_NT/8u)<<17) | ((TC_MT/16u)<<24);

    if (tid < 256) {
        // ---------------- A converters -------------------------------------
        const int r    = tid >> 1;          // row 0..127
        const int half = tid & 1;           // 0..1 (32-col half)
        const float* xp = x + (size_t)(bM + r) * Dn + (size_t)half * 32;
        const uint32_t rowbase = (uint32_t)(r * 128 + half * 64);
        uint32_t dph[2] = {0, 0};
        int i = 0;
        for (int db = 0; db < 16; db++) {
            float xr[32];
            const float4* xv = (const float4*)(xp + db * 64);
            #pragma unroll
            for (int q = 0; q < 8; q++) {
                float4 f = xv[q];
                xr[4*q] = f.x; xr[4*q+1] = f.y; xr[4*q+2] = f.z; xr[4*q+3] = f.w;
            }
            for (int e = 0; e < 16; e++, i++) {
                int s = i & 1;
                uint32_t mdn = s ? mb_dn1 : mb_dn0;
                uint32_t maf = s ? mb_af1 : mb_af0;
                if (i >= 2) { MBAR_WAIT(mdn, dph[s]); dph[s] ^= 1; }
                float g = gs[r * 17 + e];
                uint32_t hw[16], lw[16];
                #pragma unroll
                for (int j = 0; j < 16; j++)
                    bsplit2(g * xr[2*j], g * xr[2*j+1], hw[j], lw[j]);
                unsigned char* ah = smc + SM_A(s);
                unsigned char* al = smc + SM_AL(s);
                #pragma unroll
                for (int q = 0; q < 4; q++) {
                    uint32_t off = SWZ(rowbase + q * 16);
                    *(uint4*)(ah + off) = make_uint4(hw[4*q], hw[4*q+1], hw[4*q+2], hw[4*q+3]);
                    *(uint4*)(al + off) = make_uint4(lw[4*q], lw[4*q+1], lw[4*q+2], lw[4*q+3]);
                }
                asm volatile("fence.proxy.async.shared::cta;" ::: "memory");
                MBAR_ARRIVE(maf);
            }
        }
        // bias chunk (i == 256): cols 0..15 = gates, rest 0
        {
            int s = 0;
            MBAR_WAIT(mb_dn0, dph[0]); dph[0] ^= 1;
            uint32_t hw[16], lw[16];
            #pragma unroll
            for (int j = 0; j < 16; j++) {
                int c0 = half * 32 + 2 * j;
                float v0 = (c0     < 16) ? gs[r * 17 + c0]     : 0.f;
                float v1 = (c0 + 1 < 16) ? gs[r * 17 + c0 + 1] : 0.f;
                bsplit2(v0, v1, hw[j], lw[j]);
            }
            unsigned char* ah = smc + SM_A(s);
            unsigned char* al = smc + SM_AL(s);
            #pragma unroll
            for (int q = 0; q < 4; q++) {
                uint32_t off = SWZ(rowbase + q * 16);
                *(uint4*)(ah + off) = make_uint4(hw[4*q], hw[4*q+1], hw[4*q+2], hw[4*q+3]);
                *(uint4*)(al + off) = make_uint4(lw[4*q], lw[4*q+1], lw[4*q+2], lw[4*q+3]);
            }
            asm volatile("fence.proxy.async.shared::cta;" ::: "memory");
            MBAR_ARRIVE(mb_af0);
        }
    } else if (tid == 256) {
        // ---------------- B producer ----------------------------------------
        const unsigned char* pBh = g_Bh + (size_t)nt * TC_NCH * TC_BTILE;
        const unsigned char* pBl = g_Bl + (size_t)nt * TC_NCH * TC_BTILE;
        uint32_t dph[2] = {0, 0};
        for (int i = 0; i <= 256; i++) {
            int s = i & 1;
            uint32_t mdn = s ? mb_dn1 : mb_dn0;
            uint32_t mbf = s ? mb_bf1 : mb_bf0;
            if (i >= 2) { MBAR_WAIT(mdn, dph[s]); dph[s] ^= 1; }
            int cB = (i < 256) ? ((i & 15) * 16 + (i >> 4)) : 256;
            MBAR_EXPECT_TX(mbf, 2 * TC_BTILE);
            bulk_g2s(sb + SM_B(s),  pBh + (size_t)cB * TC_BTILE, TC_BTILE, mbf);
            bulk_g2s(sb + SM_BL(s), pBl + (size_t)cB * TC_BTILE, TC_BTILE, mbf);
        }
    } else if (tid == 288) {
        // ---------------- MMA issuer ----------------------------------------
        uint32_t aph[2] = {0, 0}, bph[2] = {0, 0};
        uint32_t acc = 0;
        for (int i = 0; i <= 256; i++) {
            int s = i & 1;
            uint32_t maf = s ? mb_af1 : mb_af0;
            uint32_t mbf = s ? mb_bf1 : mb_bf0;
            MBAR_WAIT(maf, aph[s]); aph[s] ^= 1;
            MBAR_WAIT(mbf, bph[s]); bph[s] ^= 1;
            uint64_t dah = DESC_BASE | ((uint64_t)((sb + SM_A(s))  >> 4) & 0x3FFF);
            uint64_t dal = DESC_BASE | ((uint64_t)((sb + SM_AL(s)) >> 4) & 0x3FFF);
            uint64_t dbh = DESC_BASE | ((uint64_t)((sb + SM_B(s))  >> 4) & 0x3FFF);
            uint64_t dbl = DESC_BASE | ((uint64_t)((sb + SM_BL(s)) >> 4) & 0x3FFF);
            #pragma unroll
            for (int ks = 0; ks < 4; ks++) {
                asm volatile("{ .reg .pred p; setp.ne.u32 p, %5, 0;\n"
                    "tcgen05.mma.cta_group::1.kind::f16 [%0], %1, %2, %3, {%4,%4,%4,%4}, p; }"
                    :: "r"(tmem), "l"(dah + ks*2), "l"(dbh + ks*2), "r"(GIDESC), "r"(0u), "r"(acc) : "memory");
                acc = 1;
                asm volatile("{ .reg .pred p; setp.ne.u32 p, %5, 0;\n"
                    "tcgen05.mma.cta_group::1.kind::f16 [%0], %1, %2, %3, {%4,%4,%4,%4}, p; }"
                    :: "r"(tmem), "l"(dal + ks*2), "l"(dbh + ks*2), "r"(GIDESC), "r"(0u), "r"(1u) : "memory");
                asm volatile("{ .reg .pred p; setp.ne.u32 p, %5, 0;\n"
                    "tcgen05.mma.cta_group::1.kind::f16 [%0], %1, %2, %3, {%4,%4,%4,%4}, p; }"
                    :: "r"(tmem), "l"(dah + ks*2), "l"(dbl + ks*2), "r"(GIDESC), "r"(0u), "r"(1u) : "memory");
            }
            uint32_t mtarget = (i == 256) ? mb_done : (s ? mb_dn1 : mb_dn0);
            asm volatile("tcgen05.commit.cta_group::1.mbarrier::arrive::one.shared::cluster.b64 [%0];" :: "r"(mtarget) : "memory");
        }
    }

    // ---------------- epilogue -----------------------------------------------
    MBAR_WAIT(mb_done, 0);
    asm volatile("tcgen05.fence::after_thread_sync;" ::: "memory");

    if (wid < 4) {
        int row = bM + wid * 32 + lane;
        float* orow = out + (size_t)row * Hn + nt * TC_NT;
        #pragma unroll
        for (int cc = 0; cc < 8; cc++) {
            uint32_t r[32];
            asm volatile(
                "tcgen05.ld.sync.aligned.32x32b.x32.b32 "
                "{%0,%1,%2,%3,%4,%5,%6,%7,%8,%9,%10,%11,%12,%13,%14,%15,"
                "%16,%17,%18,%19,%20,%21,%22,%23,%24,%25,%26,%27,%28,%29,%30,%31}, [%32];"
                : "=r"(r[0]),"=r"(r[1]),"=r"(r[2]),"=r"(r[3]),"=r"(r[4]),"=r"(r[5]),"=r"(r[6]),"=r"(r[7]),
                  "=r"(r[8]),"=r"(r[9]),"=r"(r[10]),"=r"(r[11]),"=r"(r[12]),"=r"(r[13]),"=r"(r[14]),"=r"(r[15]),
                  "=r"(r[16]),"=r"(r[17]),"=r"(r[18]),"=r"(r[19]),"=r"(r[20]),"=r"(r[21]),"=r"(r[22]),"=r"(r[23]),
                  "=r"(r[24]),"=r"(r[25]),"=r"(r[26]),"=r"(r[27]),"=r"(r[28]),"=r"(r[29]),"=r"(r[30]),"=r"(r[31])
                : "r"(tmem + cc * 32));
            asm volatile("tcgen05.wait::ld.sync.aligned;" ::: "memory");
            #pragma unroll
            for (int q = 0; q < 8; q++) {
                *(float4*)(orow + cc * 32 + q * 4) = make_float4(
                    __uint_as_float(r[q*4+0]), __uint_as_float(r[q*4+1]),
                    __uint_as_float(r[q*4+2]), __uint_as_float(r[q*4+3]));
            }
        }
    }
    __syncthreads();
    if (wid == 9)
        asm volatile("tcgen05.dealloc.cta_group::1.sync.aligned.b32 %0, %1;" :: "r"(tmem), "r"((uint32_t)TC_NT));
#endif
}

// =============================================================================
//  PATH B: tf32 mma.sync GEMM fallback (base-target legal)
// =============================================================================
#define BM 128
#define BN 128
#define BK 32
#define STAGES 4
#define ASTR 44
#define BSTR 136
#define GSTR 17
#define A_ST_FLT (BM * ASTR)
#define B_ST_FLT (BK * BSTR)
#define NTILES (En * Dn / BK)

__global__ __launch_bounds__(256, 1) void k_gemm_mma(
    const float* __restrict__ x, const float* __restrict__ ew,
    const float* __restrict__ eb, float* __restrict__ out)
{
    if (g_tc) return;

    extern __shared__ float sm[];
    float* As  = sm;
    float* Bs  = sm + STAGES * A_ST_FLT;
    float* gs  = Bs + STAGES * B_ST_FLT;
    float* ebs = gs + BM * GSTR;

    const int tid  = threadIdx.x;
    const int lane = tid & 31;
    const int wid  = tid >> 5;
    const int wm   = wid >> 2;
    const int wn   = wid & 3;
    const int grp  = lane >> 2;
    const int qid  = lane & 3;
    const int bM = blockIdx.y * BM;
    const int bN = blockIdx.x * BN;

    for (int i = tid; i < BM * En; i += 256) {
        int r = i >> 4, e = i & 15;
        gs[r * GSTR + e] = g_gates[(size_t)(bM + r) * En + e];
    }
    for (int i = tid; i < En * BN; i += 256) {
        int e = i >> 7, c = i & 127;
        ebs[e * BN + c] = eb[(size_t)e * Hn + bN + c];
    }

    const uint32_t sbase = smem_u32(sm);
    const int ar = tid >> 1, ac = (tid & 1) * 4;
    const int bk0 = tid >> 5, bc0 = (tid & 31) * 4;
    const uint32_t adst0 = sbase + (uint32_t)(ar * ASTR + ac) * 4u;
    const uint32_t bdst0 = sbase + (uint32_t)(STAGES * A_ST_FLT + bk0 * BSTR + bc0) * 4u;

#define LOAD_TILE(kt, s) do {                                                   \
        int _d0 = ((kt) * BK) & (Dn - 1);                                       \
        cpa16(adst0 + (uint32_t)((s) * A_ST_FLT * 4),                           \
              x + (size_t)(bM + ar) * Dn + _d0 + ac);                           \
        const float* _bw = ew + (size_t)((kt) * BK + bk0) * Hn + bN + bc0;      \
        uint32_t _bd = bdst0 + (uint32_t)((s) * B_ST_FLT * 4);                  \
        cpa16(_bd,                      _bw);                                   \
        cpa16(_bd + 8u*BSTR*4u,         _bw + (size_t)8  * Hn);                 \
        cpa16(_bd + 16u*BSTR*4u,        _bw + (size_t)16 * Hn);                 \
        cpa16(_bd + 24u*BSTR*4u,        _bw + (size_t)24 * Hn);                 \
    } while (0)

    #pragma unroll
    for (int s = 0; s < STAGES - 1; s++) { LOAD_TILE(s, s); CPA_COMMIT(); }

    float acc[4][4][4];
    #pragma unroll
    for (int mi = 0; mi < 4; mi++)
        #pragma unroll
        for (int ni = 0; ni < 4; ni++)
            #pragma unroll
            for (int q = 0; q < 4; q++) acc[mi][ni][q] = 0.f;

    const int aoff = (wm * 64 + grp) * ASTR + qid;
    const int boff = qid * BSTR + wn * 32 + grp;

    float g0[4], g1[4];
    __syncthreads();

    for (int kt = 0; kt < NTILES; kt++) {
        CPA_WAIT2();
        __syncthreads();

        if ((kt & 31) == 0) {
            int e = kt >> 5;
            #pragma unroll
            for (int mi = 0; mi < 4; mi++) {
                g0[mi] = gs[(wm * 64 + mi * 16 + grp) * GSTR + e];
                g1[mi] = gs[(wm * 64 + mi * 16 + grp + 8) * GSTR + e];
            }
        }

        int nk = kt + STAGES - 1;
        if (nk < NTILES) LOAD_TILE(nk, nk & (STAGES - 1));
        CPA_COMMIT();

        const float* Ap = As + (kt & (STAGES - 1)) * A_ST_FLT + aoff;
        const float* Bp = Bs + (kt & (STAGES - 1)) * B_ST_FLT + boff;

        #pragma unroll
        for (int ks = 0; ks < 4; ks++) {
            uint32_t bf[4][2];
            #pragma unroll
            for (int ni = 0; ni < 4; ni++) {
                bf[ni][0] = f2tf(Bp[(ks * 8) * BSTR + ni * 8]);
                bf[ni][1] = f2tf(Bp[(ks * 8 + 4) * BSTR + ni * 8]);
            }
            #pragma unroll
            for (int mi = 0; mi < 4; mi++) {
                const float* ab = Ap + mi * 16 * ASTR + ks * 8;
                uint32_t a0 = f2tf(g0[mi] * ab[0]);
                uint32_t a1 = f2tf(g1[mi] * ab[8 * ASTR]);
                uint32_t a2 = f2tf(g0[mi] * ab[4]);
                uint32_t a3 = f2tf(g1[mi] * ab[8 * ASTR + 4]);
                #pragma unroll
                for (int ni = 0; ni < 4; ni++)
                    mma_tf32(acc[mi][ni], a0, a1, a2, a3, bf[ni][0], bf[ni][1]);
            }
        }
    }

    #pragma unroll
    for (int mi = 0; mi < 4; mi++) {
        int r0 = wm * 64 + mi * 16 + grp;
        #pragma unroll
        for (int e = 0; e < En; e++) {
            float ge0 = gs[r0 * GSTR + e];
            float ge1 = gs[(r0 + 8) * GSTR + e];
            #pragma unroll
            for (int ni = 0; ni < 4; ni++) {
                int c0 = wn * 32 + ni * 8 + 2 * qid;
                float b0v = ebs[e * BN + c0];
                float b1v = ebs[e * BN + c0 + 1];
                acc[mi][ni][0] = fmaf(ge0, b0v, acc[mi][ni][0]);
                acc[mi][ni][1] = fmaf(ge0, b1v, acc[mi][ni][1]);
                acc[mi][ni][2] = fmaf(ge1, b0v, acc[mi][ni][2]);
                acc[mi][ni][3] = fmaf(ge1, b1v, acc[mi][ni][3]);
            }
        }
    }

    #pragma unroll
    for (int mi = 0; mi < 4; mi++) {
        int r0 = bM + wm * 64 + mi * 16 + grp;
        #pragma unroll
        for (int ni = 0; ni < 4; ni++) {
            int c0 = bN + wn * 32 + ni * 8 + 2 * qid;
            *(float2*)(out + (size_t)r0 * Hn + c0)       = make_float2(acc[mi][ni][0], acc[mi][ni][1]);
            *(float2*)(out + (size_t)(r0 + 8) * Hn + c0) = make_float2(acc[mi][ni][2], acc[mi][ni][3]);
        }
    }
#undef LOAD_TILE
}

// ---------------- launch ------------------------------------------------------
extern "C" void kernel_launch(void* const* d_in, const int* in_sizes, int n_in,
                              void* d_out, int out_size)
{
    const float* x     = (const float*)d_in[0];
    const float* wg    = (const float*)d_in[1];
    const float* wn    = (const float*)d_in[2];
    const float* ew    = (const float*)d_in[3];
    const float* eb    = (const float*)d_in[4];
    const float* noise = (const float*)d_in[5];
    float* out = (float*)d_out;

    static const int MMA_SMEM = (STAGES * (A_ST_FLT + B_ST_FLT) + BM * GSTR + En * BN) * 4;
    cudaFuncSetAttribute(k_gemm_tc2, cudaFuncAttributeMaxDynamicSharedMemorySize, GEMM2_SMEM);
    cudaFuncSetAttribute(k_gemm_mma, cudaFuncAttributeMaxDynamicSharedMemorySize, MMA_SMEM);

    k_init<<<1, 32>>>();
    k_logits<<<Bn, 1024>>>(x, wg, wn, noise);
    k_gate<<<Bn / 256, 256>>>();
    k_loss<<<1, 32>>>(out);

    // tcgen05 path (no-ops when compiled for base sm_103)
    k_prep_b<<<dim3(16, 256), 256>>>(ew);
    k_prep_bb<<<4, 256>>>(eb);
    k_gemm_tc2<<<dim3(Hn / TC_NT, Bn / TC_MT), 320, GEMM2_SMEM>>>(x, out);

    // mma.sync fallback (early-exits if tc path is live)
    k_gemm_mma<<<dim3(Hn / BN, Bn / BM), 256, MMA_SMEM>>>(x, ew, eb, out);
}

// round 5
// speedup vs baseline: 10.6574x; 1.5787x over previous
#include <cuda_runtime.h>
#include <cuda_bf16.h>
#include <math.h>
#include <stdint.h>

#define Bn 8192
#define Dn 1024
#define En 16
#define Hn 1024

// ---------- arch-feature gate for tcgen05 (compiles away on base sm_103) ----
#if defined(__CUDA_ARCH__) && (defined(__CUDA_ARCH_FEAT_SM103_ALL) || defined(__CUDA_ARCH_FEAT_SM100_ALL) || defined(__CUDA_ARCH_FAMILY_SPECIFIC__))
#define HAS_TC 1
#else
#define HAS_TC 0
#endif

// ---------------- scratch ---------------------------------------------------
__device__ float g_clean[Bn * En];
__device__ float g_stddev[Bn * En];
__device__ float g_noisy[Bn * En];
__device__ float g_gates[Bn * En];
__device__ float g_importance[En];
__device__ float g_load[En];
__device__ int   g_tc;

#define TC_NCH 257
#define TC_BTILE 32768
__device__ __align__(1024) unsigned char g_Bh[(size_t)4 * TC_NCH * TC_BTILE];
__device__ __align__(1024) unsigned char g_Bl[(size_t)4 * TC_NCH * TC_BTILE];

#define SWZ(b) ((b) ^ (((b) >> 3) & 0x70))

// ---------------- PTX helpers ------------------------------------------------
__device__ __forceinline__ uint32_t smem_u32(const void* p) {
    uint32_t a;
    asm("{ .reg .u64 t; cvta.to.shared.u64 t, %1; cvt.u32.u64 %0, t; }" : "=r"(a) : "l"(p));
    return a;
}
__device__ __forceinline__ uint32_t ctarank() {
    uint32_t r; asm("mov.u32 %0, %%cluster_ctarank;" : "=r"(r)); return r;
}
#define MBAR_INIT(a, c) asm volatile("mbarrier.init.shared.b64 [%0], %1;" :: "r"(a), "r"((uint32_t)(c)) : "memory")
#define MBAR_EXPECT_TX(a, n) asm volatile("mbarrier.arrive.expect_tx.shared.b64 _, [%0], %1;" :: "r"(a), "r"((uint32_t)(n)) : "memory")
#define MBAR_ARRIVE(a) asm volatile("mbarrier.arrive.shared.b64 _, [%0];" :: "r"(a) : "memory")
#define MBAR_WAIT(a, ph) do {                                                   \
    uint32_t _m = (a), _p = (ph), _d;                                           \
    asm volatile("{ .reg .pred p; mbarrier.try_wait.parity.acquire.cta.shared::cta.b64 p, [%1], %2; selp.b32 %0,1,0,p; }" \
        : "=r"(_d) : "r"(_m), "r"(_p) : "memory");                              \
    if (!_d) {                                                                  \
        asm volatile("{ .reg .pred P1; W%=: mbarrier.try_wait.parity.acquire.cta.shared::cta.b64 P1, [%0], %1, 0x989680; @P1 bra.uni D%=; bra.uni W%=; D%=: }" \
            :: "r"(_m), "r"(_p) : "memory");                                    \
    }                                                                           \
} while (0)
#define CLUSTER_SYNC() do {                                                     \
    asm volatile("barrier.cluster.arrive.aligned;" ::: "memory");               \
    asm volatile("barrier.cluster.wait.aligned;" ::: "memory");                 \
} while (0)

__device__ __forceinline__ void bulk_g2s_mc(uint32_t dst, const void* src, uint32_t bytes,
                                            uint32_t mbar, uint16_t mask) {
    asm volatile("cp.async.bulk.shared::cluster.global.mbarrier::complete_tx::bytes.multicast::cluster "
        "[%0], [%1], %2, [%3], %4;"
        :: "r"(dst), "l"(src), "r"(bytes), "r"(mbar), "h"(mask) : "memory");
}
__device__ __forceinline__ void cpa16(uint32_t d, const void* s) {
    asm volatile("cp.async.cg.shared.global [%0], [%1], 16;" :: "r"(d), "l"(s) : "memory");
}
#define CPA_COMMIT() asm volatile("cp.async.commit_group;" ::: "memory")
#define CPA_WAIT2()  asm volatile("cp.async.wait_group 2;" ::: "memory")

__device__ __forceinline__ uint32_t f2tf(float v) {
    uint32_t r; asm("cvt.rna.tf32.f32 %0, %1;" : "=r"(r) : "f"(v)); return r;
}
__device__ __forceinline__ void mma_tf32(float* c, uint32_t a0, uint32_t a1, uint32_t a2, uint32_t a3,
                                         uint32_t b0, uint32_t b1) {
    asm volatile("mma.sync.aligned.m16n8k8.row.col.f32.tf32.tf32.f32 "
        "{%0,%1,%2,%3},{%4,%5,%6,%7},{%8,%9},{%0,%1,%2,%3};"
        : "+f"(c[0]), "+f"(c[1]), "+f"(c[2]), "+f"(c[3])
        : "r"(a0), "r"(a1), "r"(a2), "r"(a3), "r"(b0), "r"(b1));
}

union U8 { unsigned short s[8]; uint4 v; };
__device__ __forceinline__ void bsplit(float v, unsigned short& h, unsigned short& l) {
    __nv_bfloat16 hb = __float2bfloat16(v);
    h = __bfloat16_as_ushort(hb);
    l = __bfloat16_as_ushort(__float2bfloat16(v - __bfloat162float(hb)));
}
__device__ __forceinline__ void bsplit2(float v0, float v1, uint32_t& hw, uint32_t& lw) {
    __nv_bfloat16 h0 = __float2bfloat16(v0);
    __nv_bfloat16 h1 = __float2bfloat16(v1);
    float r0 = v0 - __bfloat162float(h0);
    float r1 = v1 - __bfloat162float(h1);
    __nv_bfloat162 hp = __halves2bfloat162(h0, h1);
    __nv_bfloat162 lp = __halves2bfloat162(__float2bfloat16(r0), __float2bfloat16(r1));
    hw = *(uint32_t*)&hp;
    lw = *(uint32_t*)&lp;
}

// ---------------- kernel 0: init ---------------------------------------------
__global__ void k_init() {
    int t = threadIdx.x;
    if (t < En) { g_importance[t] = 0.f; g_load[t] = 0.f; }
    if (t == 0) g_tc = HAS_TC;
}

// ---------------- kernel 1: gating logits (8 rows / block) -------------------
__global__ __launch_bounds__(1024) void k_logits(
    const float* __restrict__ x, const float* __restrict__ wg,
    const float* __restrict__ wn, const float* __restrict__ noise)
{
    __shared__ float xs[8][1024];
    __shared__ float part[8][32];
    int tid = threadIdx.x;
    int b0 = blockIdx.x * 8;

    ((float4*)xs)[tid*2]   = ((const float4*)(x + (size_t)b0 * Dn))[tid*2];
    ((float4*)xs)[tid*2+1] = ((const float4*)(x + (size_t)b0 * Dn))[tid*2+1];
    __syncthreads();

    int w = tid >> 5, lane = tid & 31, e = w & 15;
    const float* __restrict__ W = (w < 16) ? wg : wn;
    float s[8] = {0.f,0.f,0.f,0.f,0.f,0.f,0.f,0.f};
    #pragma unroll 8
    for (int it = 0; it < 32; it++) {
        int i = lane + it * 32;
        float wv = W[i * En + e];
        #pragma unroll
        for (int r = 0; r < 8; r++) s[r] = fmaf(xs[r][i], wv, s[r]);
    }
    #pragma unroll
    for (int r = 0; r < 8; r++) {
        float v = s[r];
        #pragma unroll
        for (int off = 16; off; off >>= 1) v += __shfl_down_sync(0xffffffffu, v, off);
        if (lane == 0) part[r][w] = v;
    }
    __syncthreads();

    if (tid < 128) {
        int r = tid >> 4, e2 = tid & 15;
        int b = b0 + r;
        float clean = part[r][e2];
        float raw   = part[r][e2 + 16];
        float sp = fmaxf(raw, 0.f) + log1pf(expf(-fabsf(raw)));
        float sd = sp + 0.01f;
        float nz = clean + noise[b * En + e2] * sd;
        g_clean[b * En + e2]  = clean;
        g_stddev[b * En + e2] = sd;
        g_noisy[b * En + e2]  = nz;
    }
}

// ---------------- kernel 2: softmax / top-9 / gates / load -------------------
__global__ __launch_bounds__(256) void k_gate()
{
    int b = blockIdx.x * 256 + threadIdx.x;
    int lane = threadIdx.x & 31;

    float nz[16], cl[16], sd[16];
    #pragma unroll
    for (int i = 0; i < 4; i++) {
        float4 v = ((const float4*)(g_noisy  + (size_t)b * 16))[i];
        nz[4*i] = v.x; nz[4*i+1] = v.y; nz[4*i+2] = v.z; nz[4*i+3] = v.w;
        float4 c = ((const float4*)(g_clean  + (size_t)b * 16))[i];
        cl[4*i] = c.x; cl[4*i+1] = c.y; cl[4*i+2] = c.z; cl[4*i+3] = c.w;
        float4 s = ((const float4*)(g_stddev + (size_t)b * 16))[i];
        sd[4*i] = s.x; sd[4*i+1] = s.y; sd[4*i+2] = s.z; sd[4*i+3] = s.w;
    }

    float m = nz[0];
    #pragma unroll
    for (int e = 1; e < 16; e++) m = fmaxf(m, nz[e]);
    float p[16], sum = 0.f;
    #pragma unroll
    for (int e = 0; e < 16; e++) { p[e] = expf(nz[e] - m); sum += p[e]; }
    float inv = 1.f / sum;
    #pragma unroll
    for (int e = 0; e < 16; e++) p[e] *= inv;

    float topv[9]; int topi[9]; unsigned mask = 0;
    #pragma unroll
    for (int t = 0; t < 9; t++) {
        float best = -1.f; int bi = 0;
        #pragma unroll
        for (int e = 0; e < 16; e++) {
            bool ok = (!((mask >> e) & 1u)) && (p[e] > best);
            if (ok) { best = p[e]; bi = e; }
        }
        topv[t] = best; topi[t] = bi; mask |= (1u << bi);
    }

    float ksum = 0.f;
    #pragma unroll
    for (int t = 0; t < 8; t++) ksum += topv[t];
    float dinv = 1.f / (ksum + 1e-6f);

    float g16[16];
    #pragma unroll
    for (int e = 0; e < 16; e++) {
        float ge = 0.f;
        #pragma unroll
        for (int t = 0; t < 8; t++) ge = (topi[t] == e) ? topv[t] * dinv : ge;
        g16[e] = ge;
    }
    #pragma unroll
    for (int i = 0; i < 4; i++)
        ((float4*)(g_gates + (size_t)b * 16))[i] =
            make_float4(g16[4*i], g16[4*i+1], g16[4*i+2], g16[4*i+3]);

    float thr_in = topv[8], thr_out = topv[7];
    float ldv[16];
    #pragma unroll
    for (int e = 0; e < 16; e++) {
        bool in = nz[e] > thr_in;
        float thr = in ? thr_in : thr_out;
        float z = (cl[e] - thr) / sd[e];
        ldv[e] = 0.5f * (1.f + erff(z * 0.70710678118654752440f));
    }
    #pragma unroll
    for (int e = 0; e < 16; e++) {
        float v1 = g16[e], v2 = ldv[e];
        #pragma unroll
        for (int off = 16; off; off >>= 1) {
            v1 += __shfl_down_sync(0xffffffffu, v1, off);
            v2 += __shfl_down_sync(0xffffffffu, v2, off);
        }
        if (lane == 0) {
            atomicAdd(&g_importance[e], v1);
            atomicAdd(&g_load[e], v2);
        }
    }
}

// ---------------- kernel 3: loss ---------------------------------------------
__global__ void k_loss(float* __restrict__ out)
{
    if (threadIdx.x == 0 && blockIdx.x == 0) {
        float mi = 0.f, ml = 0.f;
        for (int e = 0; e < En; e++) { mi += g_importance[e]; ml += g_load[e]; }
        mi *= (1.f / En); ml *= (1.f / En);
        float vi = 0.f, vl = 0.f;
        for (int e = 0; e < En; e++) {
            float d1 = g_importance[e] - mi; vi += d1 * d1;
            float d2 = g_load[e] - ml;       vl += d2 * d2;
        }
        vi /= (En - 1); vl /= (En - 1);
        out[(size_t)Bn * Hn] = 0.01f * (vi / (mi * mi + 1e-10f) + vl / (ml * ml + 1e-10f));
    }
}

// ---------------- kernel 5: B = expert_w split+tiled+swizzled (tc path) ------
__global__ __launch_bounds__(256) void k_prep_b(const float* __restrict__ ew)
{
#if HAS_TC
    int h64 = blockIdx.x;
    int kc  = blockIdx.y;
    __shared__ float ts[64][65];
    int tid = threadIdx.x;
    int kl = tid >> 4;
    int h4 = (tid & 15) * 4;
    #pragma unroll
    for (int r = 0; r < 4; r++) {
        int kk = kl + r * 16;
        float4 v = *(const float4*)(ew + (size_t)(kc * 64 + kk) * Hn + h64 * 64 + h4);
        ts[h4 + 0][kk] = v.x; ts[h4 + 1][kk] = v.y;
        ts[h4 + 2][kk] = v.z; ts[h4 + 3][kk] = v.w;
    }
    __syncthreads();
    #pragma unroll
    for (int r2 = 0; r2 < 2; r2++) {
        int it = tid + r2 * 256;
        int hl = it >> 3, kg = it & 7;
        U8 hi, lo;
        #pragma unroll
        for (int j = 0; j < 8; j++) bsplit(ts[hl][kg * 8 + j], hi.s[j], lo.s[j]);
        int hg = h64 * 64 + hl;
        int ht = hg >> 8, rr = hg & 255;
        size_t addr = ((size_t)(ht * TC_NCH + kc)) * TC_BTILE + SWZ((uint32_t)(rr * 128 + kg * 16));
        *(uint4*)(g_Bh + addr) = hi.v;
        *(uint4*)(g_Bl + addr) = lo.v;
    }
#endif
}

__global__ __launch_bounds__(256) void k_prep_bb(const float* __restrict__ eb)
{
#if HAS_TC
    int ht = blockIdx.x;
    int row = threadIdx.x;
    int hg = ht * 256 + row;
    #pragma unroll
    for (int kg = 0; kg < 8; kg++) {
        U8 hi, lo;
        #pragma unroll
        for (int j = 0; j < 8; j++) {
            int c = kg * 8 + j;
            bsplit((c < 16) ? eb[c * Hn + hg] : 0.f, hi.s[j], lo.s[j]);
        }
        size_t addr = ((size_t)(ht * TC_NCH + 256)) * TC_BTILE + SWZ((uint32_t)(row * 128 + kg * 16));
        *(uint4*)(g_Bh + addr) = hi.v;
        *(uint4*)(g_Bl + addr) = lo.v;
    }
#endif
}

// =============================================================================
//  kernel 7 (tc path): fused GEMM with 2-CTA B multicast
//  cluster (1,2,1): CTAs (nt, 2m) and (nt, 2m+1) share nt -> identical B.
//  Each CTA multicasts its 128-row half of every B chunk to both CTAs.
//  warps 0-7: A converters; w8l0: B producer; w9l0: MMA issuer (cg1).
// =============================================================================
#define TC_MT 128
#define TC_NT 256
#define SM_A(s)   (1024u + (uint32_t)(s) * 32768u)
#define SM_AL(s)  (SM_A(s) + 16384u)
#define SM_B(s)   (66560u + (uint32_t)(s) * 65536u)
#define SM_BL(s)  (SM_B(s) + 32768u)
#define SM_GS     197632u
#define GEMM2_SMEM 206848

__global__ __launch_bounds__(320, 1) __cluster_dims__(1, 2, 1)
void k_gemm_tc2(const float* __restrict__ x, float* __restrict__ out)
{
#if HAS_TC
    extern __shared__ unsigned char smc[];
    const uint32_t sb = smem_u32(smc);
    const uint32_t mb_af0 = sb + 0,  mb_af1 = sb + 8;
    const uint32_t mb_bf0 = sb + 16, mb_bf1 = sb + 24;
    const uint32_t mb_dn0 = sb + 32, mb_dn1 = sb + 40;
    const uint32_t mb_done = sb + 48;
    const uint32_t tptr    = sb + 64;
    float* gs = (float*)(smc + SM_GS);

    const int tid = threadIdx.x, wid = tid >> 5, lane = tid & 31;
    const int nt = blockIdx.x, mt = blockIdx.y;
    const int bM = mt * TC_MT;
    const uint32_t rank = ctarank();

    if (tid == 0) {
        MBAR_INIT(mb_af0, 256); MBAR_INIT(mb_af1, 256);
        MBAR_INIT(mb_bf0, 1);   MBAR_INIT(mb_bf1, 1);
        MBAR_INIT(mb_dn0, 2);   MBAR_INIT(mb_dn1, 2);   // commits from BOTH issuers
        MBAR_INIT(mb_done, 2);
    }
    for (int i = tid; i < TC_MT * En; i += 320) {
        int r = i >> 4, e = i & 15;
        gs[r * 17 + e] = g_gates[(size_t)(bM + r) * En + e];
    }
    __syncthreads();
    if (wid == 9) {
        asm volatile("tcgen05.alloc.cta_group::1.sync.aligned.shared::cta.b32 [%0], %1;" :: "r"(tptr), "r"((uint32_t)TC_NT) : "memory");
        asm volatile("tcgen05.relinquish_alloc_permit.cta_group::1.sync.aligned;");
    }
    __syncthreads();
    // all mbarriers (both CTAs) must be init'd before any multicast lands
    CLUSTER_SYNC();
    uint32_t tmem;
    asm volatile("ld.shared.b32 %0, [%1];" : "=r"(tmem) : "r"(tptr));

    const uint64_t DESC_BASE =
        (uint64_t(2) << 61) | (uint64_t(1) << 46) | (uint64_t(64) << 32) | (uint64_t(1) << 16);
    const uint32_t GIDESC = (1u<<4) | (1u<<7) | (1u<<10) | ((TC_NT/8u)<<17) | ((TC_MT/16u)<<24);

    if (tid < 256) {
        // ---------------- A converters -------------------------------------
        const int r    = tid >> 1;
        const int half = tid & 1;
        const float* xp = x + (size_t)(bM + r) * Dn + (size_t)half * 32;
        const uint32_t rowbase = (uint32_t)(r * 128 + half * 64);
        uint32_t dph[2] = {0, 0};
        int i = 0;
        for (int db = 0; db < 16; db++) {
            float xr[32];
            const float4* xv = (const float4*)(xp + db * 64);
            #pragma unroll
            for (int q = 0; q < 8; q++) {
                float4 f = xv[q];
                xr[4*q] = f.x; xr[4*q+1] = f.y; xr[4*q+2] = f.z; xr[4*q+3] = f.w;
            }
            for (int e = 0; e < 16; e++, i++) {
                int s = i & 1;
                uint32_t mdn = s ? mb_dn1 : mb_dn0;
                uint32_t maf = s ? mb_af1 : mb_af0;
                if (i >= 2) { MBAR_WAIT(mdn, dph[s]); dph[s] ^= 1; }
                float g = gs[r * 17 + e];
                uint32_t hw[16], lw[16];
                #pragma unroll
                for (int j = 0; j < 16; j++)
                    bsplit2(g * xr[2*j], g * xr[2*j+1], hw[j], lw[j]);
                unsigned char* ah = smc + SM_A(s);
                unsigned char* al = smc + SM_AL(s);
                #pragma unroll
                for (int q = 0; q < 4; q++) {
                    uint32_t off = SWZ(rowbase + q * 16);
                    *(uint4*)(ah + off) = make_uint4(hw[4*q], hw[4*q+1], hw[4*q+2], hw[4*q+3]);
                    *(uint4*)(al + off) = make_uint4(lw[4*q], lw[4*q+1], lw[4*q+2], lw[4*q+3]);
                }
                asm volatile("fence.proxy.async.shared::cta;" ::: "memory");
                MBAR_ARRIVE(maf);
            }
        }
        // bias chunk (i == 256)
        {
            int s = 0;
            MBAR_WAIT(mb_dn0, dph[0]); dph[0] ^= 1;
            uint32_t hw[16], lw[16];
            #pragma unroll
            for (int j = 0; j < 16; j++) {
                int c0 = half * 32 + 2 * j;
                float v0 = (c0     < 16) ? gs[r * 17 + c0]     : 0.f;
                float v1 = (c0 + 1 < 16) ? gs[r * 17 + c0 + 1] : 0.f;
                bsplit2(v0, v1, hw[j], lw[j]);
            }
            unsigned char* ah = smc + SM_A(s);
            unsigned char* al = smc + SM_AL(s);
            #pragma unroll
            for (int q = 0; q < 4; q++) {
                uint32_t off = SWZ(rowbase + q * 16);
                *(uint4*)(ah + off) = make_uint4(hw[4*q], hw[4*q+1], hw[4*q+2], hw[4*q+3]);
                *(uint4*)(al + off) = make_uint4(lw[4*q], lw[4*q+1], lw[4*q+2], lw[4*q+3]);
            }
            asm volatile("fence.proxy.async.shared::cta;" ::: "memory");
            MBAR_ARRIVE(mb_af0);
        }
    } else if (tid == 256) {
        // ---------------- B producer: multicast cooperative slices ----------
        const unsigned char* pBh = g_Bh + (size_t)nt * TC_NCH * TC_BTILE;
        const unsigned char* pBl = g_Bl + (size_t)nt * TC_NCH * TC_BTILE;
        const uint32_t hoff = rank * 16384u;     // this CTA's 128-row half
        uint32_t dph[2] = {0, 0};
        for (int i = 0; i <= 256; i++) {
            int s = i & 1;
            uint32_t mdn = s ? mb_dn1 : mb_dn0;
            uint32_t mbf = s ? mb_bf1 : mb_bf0;
            if (i >= 2) { MBAR_WAIT(mdn, dph[s]); dph[s] ^= 1; }
            int cB = (i < 256) ? ((i & 15) * 16 + (i >> 4)) : 256;
            MBAR_EXPECT_TX(mbf, 2 * TC_BTILE);   // full chunk: 2 local + 2 peer slices
            bulk_g2s_mc(sb + SM_B(s)  + hoff, pBh + (size_t)cB * TC_BTILE + hoff, 16384u, mbf, 3);
            bulk_g2s_mc(sb + SM_BL(s) + hoff, pBl + (size_t)cB * TC_BTILE + hoff, 16384u, mbf, 3);
        }
    } else if (tid == 288) {
        // ---------------- MMA issuer (cg1, commit multicast to both CTAs) ---
        uint32_t aph[2] = {0, 0}, bph[2] = {0, 0};
        uint32_t acc = 0;
        for (int i = 0; i <= 256; i++) {
            int s = i & 1;
            uint32_t maf = s ? mb_af1 : mb_af0;
            uint32_t mbf = s ? mb_bf1 : mb_bf0;
            MBAR_WAIT(maf, aph[s]); aph[s] ^= 1;
            MBAR_WAIT(mbf, bph[s]); bph[s] ^= 1;
            uint64_t dah = DESC_BASE | ((uint64_t)((sb + SM_A(s))  >> 4) & 0x3FFF);
            uint64_t dal = DESC_BASE | ((uint64_t)((sb + SM_AL(s)) >> 4) & 0x3FFF);
            uint64_t dbh = DESC_BASE | ((uint64_t)((sb + SM_B(s))  >> 4) & 0x3FFF);
            uint64_t dbl = DESC_BASE | ((uint64_t)((sb + SM_BL(s)) >> 4) & 0x3FFF);
            #pragma unroll
            for (int ks = 0; ks < 4; ks++) {
                asm volatile("{ .reg .pred p; setp.ne.u32 p, %5, 0;\n"
                    "tcgen05.mma.cta_group::1.kind::f16 [%0], %1, %2, %3, {%4,%4,%4,%4}, p; }"
                    :: "r"(tmem), "l"(dah + ks*2), "l"(dbh + ks*2), "r"(GIDESC), "r"(0u), "r"(acc) : "memory");
                acc = 1;
                asm volatile("{ .reg .pred p; setp.ne.u32 p, %5, 0;\n"
                    "tcgen05.mma.cta_group::1.kind::f16 [%0], %1, %2, %3, {%4,%4,%4,%4}, p; }"
                    :: "r"(tmem), "l"(dal + ks*2), "l"(dbh + ks*2), "r"(GIDESC), "r"(0u), "r"(1u) : "memory");
                asm volatile("{ .reg .pred p; setp.ne.u32 p, %5, 0;\n"
                    "tcgen05.mma.cta_group::1.kind::f16 [%0], %1, %2, %3, {%4,%4,%4,%4}, p; }"
                    :: "r"(tmem), "l"(dah + ks*2), "l"(dbl + ks*2), "r"(GIDESC), "r"(0u), "r"(1u) : "memory");
            }
            // multicast commit: frees this chunk's B slices in BOTH CTAs
            uint32_t mtarget = (i == 256) ? mb_done : (s ? mb_dn1 : mb_dn0);
            asm volatile(
                "tcgen05.commit.cta_group::1.mbarrier::arrive::one.shared::cluster.multicast::cluster.b64 [%0], %1;"
                :: "r"(mtarget), "h"((uint16_t)3) : "memory");
        }
    }

    // ---------------- epilogue -----------------------------------------------
    MBAR_WAIT(mb_done, 0);
    asm volatile("tcgen05.fence::after_thread_sync;" ::: "memory");

    if (wid < 4) {
        int row = bM + wid * 32 + lane;
        float* orow = out + (size_t)row * Hn + nt * TC_NT;
        #pragma unroll
        for (int cc = 0; cc < 8; cc++) {
            uint32_t r[32];
            asm volatile(
                "tcgen05.ld.sync.aligned.32x32b.x32.b32 "
                "{%0,%1,%2,%3,%4,%5,%6,%7,%8,%9,%10,%11,%12,%13,%14,%15,"
                "%16,%17,%18,%19,%20,%21,%22,%23,%24,%25,%26,%27,%28,%29,%30,%31}, [%32];"
                : "=r"(r[0]),"=r"(r[1]),"=r"(r[2]),"=r"(r[3]),"=r"(r[4]),"=r"(r[5]),"=r"(r[6]),"=r"(r[7]),
                  "=r"(r[8]),"=r"(r[9]),"=r"(r[10]),"=r"(r[11]),"=r"(r[12]),"=r"(r[13]),"=r"(r[14]),"=r"(r[15]),
                  "=r"(r[16]),"=r"(r[17]),"=r"(r[18]),"=r"(r[19]),"=r"(r[20]),"=r"(r[21]),"=r"(r[22]),"=r"(r[23]),
                  "=r"(r[24]),"=r"(r[25]),"=r"(r[26]),"=r"(r[27]),"=r"(r[28]),"=r"(r[29]),"=r"(r[30]),"=r"(r[31])
                : "r"(tmem + cc * 32));
            asm volatile("tcgen05.wait::ld.sync.aligned;" ::: "memory");
            #pragma unroll
            for (int q = 0; q < 8; q++) {
                *(float4*)(orow + cc * 32 + q * 4) = make_float4(
                    __uint_as_float(r[q*4+0]), __uint_as_float(r[q*4+1]),
                    __uint_as_float(r[q*4+2]), __uint_as_float(r[q*4+3]));
            }
        }
    }
    __syncthreads();
    if (wid == 9)
        asm volatile("tcgen05.dealloc.cta_group::1.sync.aligned.b32 %0, %1;" :: "r"(tmem), "r"((uint32_t)TC_NT));
    CLUSTER_SYNC();   // no CTA exits while peer multicast could target its SMEM
#endif
}

// =============================================================================
//  PATH B: tf32 mma.sync GEMM fallback (base-target legal)
// =============================================================================
#define BM 128
#define BN 128
#define BK 32
#define STAGES 4
#define ASTR 44
#define BSTR 136
#define GSTR 17
#define A_ST_FLT (BM * ASTR)
#define B_ST_FLT (BK * BSTR)
#define NTILES (En * Dn / BK)

__global__ __launch_bounds__(256, 1) void k_gemm_mma(
    const float* __restrict__ x, const float* __restrict__ ew,
    const float* __restrict__ eb, float* __restrict__ out)
{
    if (g_tc) return;

    extern __shared__ float sm[];
    float* As  = sm;
    float* Bs  = sm + STAGES * A_ST_FLT;
    float* gs  = Bs + STAGES * B_ST_FLT;
    float* ebs = gs + BM * GSTR;

    const int tid  = threadIdx.x;
    const int lane = tid & 31;
    const int wid  = tid >> 5;
    const int wm   = wid >> 2;
    const int wn   = wid & 3;
    const int grp  = lane >> 2;
    const int qid  = lane & 3;
    const int bM = blockIdx.y * BM;
    const int bN = blockIdx.x * BN;

    for (int i = tid; i < BM * En; i += 256) {
        int r = i >> 4, e = i & 15;
        gs[r * GSTR + e] = g_gates[(size_t)(bM + r) * En + e];
    }
    for (int i = tid; i < En * BN; i += 256) {
        int e = i >> 7, c = i & 127;
        ebs[e * BN + c] = eb[(size_t)e * Hn + bN + c];
    }

    const uint32_t sbase = smem_u32(sm);
    const int ar = tid >> 1, ac = (tid & 1) * 4;
    const int bk0 = tid >> 5, bc0 = (tid & 31) * 4;
    const uint32_t adst0 = sbase + (uint32_t)(ar * ASTR + ac) * 4u;
    const uint32_t bdst0 = sbase + (uint32_t)(STAGES * A_ST_FLT + bk0 * BSTR + bc0) * 4u;

#define LOAD_TILE(kt, s) do {                                                   \
        int _d0 = ((kt) * BK) & (Dn - 1);                                       \
        cpa16(adst0 + (uint32_t)((s) * A_ST_FLT * 4),                           \
              x + (size_t)(bM + ar) * Dn + _d0 + ac);                           \
        const float* _bw = ew + (size_t)((kt) * BK + bk0) * Hn + bN + bc0;      \
        uint32_t _bd = bdst0 + (uint32_t)((s) * B_ST_FLT * 4);                  \
        cpa16(_bd,                      _bw);                                   \
        cpa16(_bd + 8u*BSTR*4u,         _bw + (size_t)8  * Hn);                 \
        cpa16(_bd + 16u*BSTR*4u,        _bw + (size_t)16 * Hn);                 \
        cpa16(_bd + 24u*BSTR*4u,        _bw + (size_t)24 * Hn);                 \
    } while (0)

    #pragma unroll
    for (int s = 0; s < STAGES - 1; s++) { LOAD_TILE(s, s); CPA_COMMIT(); }

    float acc[4][4][4];
    #pragma unroll
    for (int mi = 0; mi < 4; mi++)
        #pragma unroll
        for (int ni = 0; ni < 4; ni++)
            #pragma unroll
            for (int q = 0; q < 4; q++) acc[mi][ni][q] = 0.f;

    const int aoff = (wm * 64 + grp) * ASTR + qid;
    const int boff = qid * BSTR + wn * 32 + grp;

    float g0[4], g1[4];
    __syncthreads();

    for (int kt = 0; kt < NTILES; kt++) {
        CPA_WAIT2();
        __syncthreads();

        if ((kt & 31) == 0) {
            int e = kt >> 5;
            #pragma unroll
            for (int mi = 0; mi < 4; mi++) {
                g0[mi] = gs[(wm * 64 + mi * 16 + grp) * GSTR + e];
                g1[mi] = gs[(wm * 64 + mi * 16 + grp + 8) * GSTR + e];
            }
        }

        int nk = kt + STAGES - 1;
        if (nk < NTILES) LOAD_TILE(nk, nk & (STAGES - 1));
        CPA_COMMIT();

        const float* Ap = As + (kt & (STAGES - 1)) * A_ST_FLT + aoff;
        const float* Bp = Bs + (kt & (STAGES - 1)) * B_ST_FLT + boff;

        #pragma unroll
        for (int ks = 0; ks < 4; ks++) {
            uint32_t bf[4][2];
            #pragma unroll
            for (int ni = 0; ni < 4; ni++) {
                bf[ni][0] = f2tf(Bp[(ks * 8) * BSTR + ni * 8]);
                bf[ni][1] = f2tf(Bp[(ks * 8 + 4) * BSTR + ni * 8]);
            }
            #pragma unroll
            for (int mi = 0; mi < 4; mi++) {
                const float* ab = Ap + mi * 16 * ASTR + ks * 8;
                uint32_t a0 = f2tf(g0[mi] * ab[0]);
                uint32_t a1 = f2tf(g1[mi] * ab[8 * ASTR]);
                uint32_t a2 = f2tf(g0[mi] * ab[4]);
                uint32_t a3 = f2tf(g1[mi] * ab[8 * ASTR + 4]);
                #pragma unroll
                for (int ni = 0; ni < 4; ni++)
                    mma_tf32(acc[mi][ni], a0, a1, a2, a3, bf[ni][0], bf[ni][1]);
            }
        }
    }

    #pragma unroll
    for (int mi = 0; mi < 4; mi++) {
        int r0 = wm * 64 + mi * 16 + grp;
        #pragma unroll
        for (int e = 0; e < En; e++) {
            float ge0 = gs[r0 * GSTR + e];
            float ge1 = gs[(r0 + 8) * GSTR + e];
            #pragma unroll
            for (int ni = 0; ni < 4; ni++) {
                int c0 = wn * 32 + ni * 8 + 2 * qid;
                float b0v = ebs[e * BN + c0];
                float b1v = ebs[e * BN + c0 + 1];
                acc[mi][ni][0] = fmaf(ge0, b0v, acc[mi][ni][0]);
                acc[mi][ni][1] = fmaf(ge0, b1v, acc[mi][ni][1]);
                acc[mi][ni][2] = fmaf(ge1, b0v, acc[mi][ni][2]);
                acc[mi][ni][3] = fmaf(ge1, b1v, acc[mi][ni][3]);
            }
        }
    }

    #pragma unroll
    for (int mi = 0; mi < 4; mi++) {
        int r0 = bM + wm * 64 + mi * 16 + grp;
        #pragma unroll
        for (int ni = 0; ni < 4; ni++) {
            int c0 = bN + wn * 32 + ni * 8 + 2 * qid;
            *(float2*)(out + (size_t)r0 * Hn + c0)       = make_float2(acc[mi][ni][0], acc[mi][ni][1]);
            *(float2*)(out + (size_t)(r0 + 8) * Hn + c0) = make_float2(acc[mi][ni][2], acc[mi][ni][3]);
        }
    }
#undef LOAD_TILE
}

// ---------------- launch ------------------------------------------------------
extern "C" void kernel_launch(void* const* d_in, const int* in_sizes, int n_in,
                              void* d_out, int out_size)
{
    const float* x     = (const float*)d_in[0];
    const float* wg    = (const float*)d_in[1];
    const float* wn    = (const float*)d_in[2];
    const float* ew    = (const float*)d_in[3];
    const float* eb    = (const float*)d_in[4];
    const float* noise = (const float*)d_in[5];
    float* out = (float*)d_out;

    static const int MMA_SMEM = (STAGES * (A_ST_FLT + B_ST_FLT) + BM * GSTR + En * BN) * 4;
    cudaFuncSetAttribute(k_gemm_tc2, cudaFuncAttributeMaxDynamicSharedMemorySize, GEMM2_SMEM);
    cudaFuncSetAttribute(k_gemm_mma, cudaFuncAttributeMaxDynamicSharedMemorySize, MMA_SMEM);

    k_init<<<1, 32>>>();
    k_logits<<<Bn / 8, 1024>>>(x, wg, wn, noise);
    k_gate<<<Bn / 256, 256>>>();
    k_loss<<<1, 32>>>(out);

    // tcgen05 path (no-ops when compiled for base sm_103)
    k_prep_b<<<dim3(16, 256), 256>>>(ew);
    k_prep_bb<<<4, 256>>>(eb);
    k_gemm_tc2<<<dim3(Hn / TC_NT, Bn / TC_MT), 320, GEMM2_SMEM>>>(x, out);

    // mma.sync fallback (early-exits if tc path is live)
    k_gemm_mma<<<dim3(Hn / BN, Bn / BM), 256, MMA_SMEM>>>(x, ew, eb, out);
}

// round 6
// speedup vs baseline: 11.6421x; 1.0924x over previous
#include <cuda_runtime.h>
#include <cuda_bf16.h>
#include <math.h>
#include <stdint.h>

#define Bn 8192
#define Dn 1024
#define En 16
#define Hn 1024

// ---------- arch-feature gate for tcgen05 (compiles away on base sm_103) ----
#if defined(__CUDA_ARCH__) && (defined(__CUDA_ARCH_FEAT_SM103_ALL) || defined(__CUDA_ARCH_FEAT_SM100_ALL) || defined(__CUDA_ARCH_FAMILY_SPECIFIC__))
#define HAS_TC 1
#else
#define HAS_TC 0
#endif

// ---------------- scratch ---------------------------------------------------
__device__ float g_clean[Bn * En];
__device__ float g_stddev[Bn * En];
__device__ float g_noisy[Bn * En];
__device__ float g_gates[Bn * En];
__device__ float g_importance[En];
__device__ float g_load[En];
__device__ int   g_tc;

// B operand: tf32 (rna-rounded f32), tiled [4 nt][257 ch][64KB].
// chunk layout: [sub(2)][256 rows x 128B (32 tf32 cols), SW128 swizzled]
#define TC_NCH 257
#define TC_BCHUNK 65536
__device__ __align__(1024) unsigned char g_Bt[(size_t)4 * TC_NCH * TC_BCHUNK];

#define SWZ(b) ((b) ^ (((b) >> 3) & 0x70))

// ---------------- PTX helpers ------------------------------------------------
__device__ __forceinline__ uint32_t smem_u32(const void* p) {
    uint32_t a;
    asm("{ .reg .u64 t; cvta.to.shared.u64 t, %1; cvt.u32.u64 %0, t; }" : "=r"(a) : "l"(p));
    return a;
}
__device__ __forceinline__ uint32_t ctarank() {
    uint32_t r; asm("mov.u32 %0, %%cluster_ctarank;" : "=r"(r)); return r;
}
#define MBAR_INIT(a, c) asm volatile("mbarrier.init.shared.b64 [%0], %1;" :: "r"(a), "r"((uint32_t)(c)) : "memory")
#define MBAR_EXPECT_TX(a, n) asm volatile("mbarrier.arrive.expect_tx.shared.b64 _, [%0], %1;" :: "r"(a), "r"((uint32_t)(n)) : "memory")
#define MBAR_ARRIVE(a) asm volatile("mbarrier.arrive.shared.b64 _, [%0];" :: "r"(a) : "memory")
#define MBAR_WAIT(a, ph) do {                                                   \
    uint32_t _m = (a), _p = (ph), _d;                                           \
    asm volatile("{ .reg .pred p; mbarrier.try_wait.parity.acquire.cta.shared::cta.b64 p, [%1], %2; selp.b32 %0,1,0,p; }" \
        : "=r"(_d) : "r"(_m), "r"(_p) : "memory");                              \
    if (!_d) {                                                                  \
        asm volatile("{ .reg .pred P1; W%=: mbarrier.try_wait.parity.acquire.cta.shared::cta.b64 P1, [%0], %1, 0x989680; @P1 bra.uni D%=; bra.uni W%=; D%=: }" \
            :: "r"(_m), "r"(_p) : "memory");                                    \
    }                                                                           \
} while (0)
#define CLUSTER_SYNC() do {                                                     \
    asm volatile("barrier.cluster.arrive.aligned;" ::: "memory");               \
    asm volatile("barrier.cluster.wait.aligned;" ::: "memory");                 \
} while (0)

__device__ __forceinline__ void bulk_g2s_mc(uint32_t dst, const void* src, uint32_t bytes,
                                            uint32_t mbar, uint16_t mask) {
    asm volatile("cp.async.bulk.shared::cluster.global.mbarrier::complete_tx::bytes.multicast::cluster "
        "[%0], [%1], %2, [%3], %4;"
        :: "r"(dst), "l"(src), "r"(bytes), "r"(mbar), "h"(mask) : "memory");
}
__device__ __forceinline__ void cpa16(uint32_t d, const void* s) {
    asm volatile("cp.async.cg.shared.global [%0], [%1], 16;" :: "r"(d), "l"(s) : "memory");
}
#define CPA_COMMIT() asm volatile("cp.async.commit_group;" ::: "memory")
#define CPA_WAIT2()  asm volatile("cp.async.wait_group 2;" ::: "memory")

__device__ __forceinline__ uint32_t f2tf(float v) {
    uint32_t r; asm("cvt.rna.tf32.f32 %0, %1;" : "=r"(r) : "f"(v)); return r;
}
__device__ __forceinline__ void mma_tf32(float* c, uint32_t a0, uint32_t a1, uint32_t a2, uint32_t a3,
                                         uint32_t b0, uint32_t b1) {
    asm volatile("mma.sync.aligned.m16n8k8.row.col.f32.tf32.tf32.f32 "
        "{%0,%1,%2,%3},{%4,%5,%6,%7},{%8,%9},{%0,%1,%2,%3};"
        : "+f"(c[0]), "+f"(c[1]), "+f"(c[2]), "+f"(c[3])
        : "r"(a0), "r"(a1), "r"(a2), "r"(a3), "r"(b0), "r"(b1));
}

// ---------------- kernel 0: init ---------------------------------------------
__global__ void k_init() {
    int t = threadIdx.x;
    if (t < En) { g_importance[t] = 0.f; g_load[t] = 0.f; }
    if (t == 0) g_tc = HAS_TC;
}

// ---------------- kernel 1: gating logits (8 rows / block) -------------------
__global__ __launch_bounds__(1024) void k_logits(
    const float* __restrict__ x, const float* __restrict__ wg,
    const float* __restrict__ wn, const float* __restrict__ noise)
{
    __shared__ float xs[8][1024];
    __shared__ float part[8][32];
    int tid = threadIdx.x;
    int b0 = blockIdx.x * 8;

    ((float4*)xs)[tid*2]   = ((const float4*)(x + (size_t)b0 * Dn))[tid*2];
    ((float4*)xs)[tid*2+1] = ((const float4*)(x + (size_t)b0 * Dn))[tid*2+1];
    __syncthreads();

    int w = tid >> 5, lane = tid & 31, e = w & 15;
    const float* __restrict__ W = (w < 16) ? wg : wn;
    float s[8] = {0.f,0.f,0.f,0.f,0.f,0.f,0.f,0.f};
    #pragma unroll 8
    for (int it = 0; it < 32; it++) {
        int i = lane + it * 32;
        float wv = W[i * En + e];
        #pragma unroll
        for (int r = 0; r < 8; r++) s[r] = fmaf(xs[r][i], wv, s[r]);
    }
    #pragma unroll
    for (int r = 0; r < 8; r++) {
        float v = s[r];
        #pragma unroll
        for (int off = 16; off; off >>= 1) v += __shfl_down_sync(0xffffffffu, v, off);
        if (lane == 0) part[r][w] = v;
    }
    __syncthreads();

    if (tid < 128) {
        int r = tid >> 4, e2 = tid & 15;
        int b = b0 + r;
        float clean = part[r][e2];
        float raw   = part[r][e2 + 16];
        float sp = fmaxf(raw, 0.f) + log1pf(expf(-fabsf(raw)));
        float sd = sp + 0.01f;
        float nz = clean + noise[b * En + e2] * sd;
        g_clean[b * En + e2]  = clean;
        g_stddev[b * En + e2] = sd;
        g_noisy[b * En + e2]  = nz;
    }
}

// ---------------- kernel 2: softmax / top-9 / gates / load -------------------
__global__ __launch_bounds__(256) void k_gate()
{
    int b = blockIdx.x * 256 + threadIdx.x;
    int lane = threadIdx.x & 31;

    float nz[16], cl[16], sd[16];
    #pragma unroll
    for (int i = 0; i < 4; i++) {
        float4 v = ((const float4*)(g_noisy  + (size_t)b * 16))[i];
        nz[4*i] = v.x; nz[4*i+1] = v.y; nz[4*i+2] = v.z; nz[4*i+3] = v.w;
        float4 c = ((const float4*)(g_clean  + (size_t)b * 16))[i];
        cl[4*i] = c.x; cl[4*i+1] = c.y; cl[4*i+2] = c.z; cl[4*i+3] = c.w;
        float4 s = ((const float4*)(g_stddev + (size_t)b * 16))[i];
        sd[4*i] = s.x; sd[4*i+1] = s.y; sd[4*i+2] = s.z; sd[4*i+3] = s.w;
    }

    float m = nz[0];
    #pragma unroll
    for (int e = 1; e < 16; e++) m = fmaxf(m, nz[e]);
    float p[16], sum = 0.f;
    #pragma unroll
    for (int e = 0; e < 16; e++) { p[e] = expf(nz[e] - m); sum += p[e]; }
    float inv = 1.f / sum;
    #pragma unroll
    for (int e = 0; e < 16; e++) p[e] *= inv;

    float topv[9]; int topi[9]; unsigned mask = 0;
    #pragma unroll
    for (int t = 0; t < 9; t++) {
        float best = -1.f; int bi = 0;
        #pragma unroll
        for (int e = 0; e < 16; e++) {
            bool ok = (!((mask >> e) & 1u)) && (p[e] > best);
            if (ok) { best = p[e]; bi = e; }
        }
        topv[t] = best; topi[t] = bi; mask |= (1u << bi);
    }

    float ksum = 0.f;
    #pragma unroll
    for (int t = 0; t < 8; t++) ksum += topv[t];
    float dinv = 1.f / (ksum + 1e-6f);

    float g16[16];
    #pragma unroll
    for (int e = 0; e < 16; e++) {
        float ge = 0.f;
        #pragma unroll
        for (int t = 0; t < 8; t++) ge = (topi[t] == e) ? topv[t] * dinv : ge;
        g16[e] = ge;
    }
    #pragma unroll
    for (int i = 0; i < 4; i++)
        ((float4*)(g_gates + (size_t)b * 16))[i] =
            make_float4(g16[4*i], g16[4*i+1], g16[4*i+2], g16[4*i+3]);

    float thr_in = topv[8], thr_out = topv[7];
    float ldv[16];
    #pragma unroll
    for (int e = 0; e < 16; e++) {
        bool in = nz[e] > thr_in;
        float thr = in ? thr_in : thr_out;
        float z = (cl[e] - thr) / sd[e];
        ldv[e] = 0.5f * (1.f + erff(z * 0.70710678118654752440f));
    }
    #pragma unroll
    for (int e = 0; e < 16; e++) {
        float v1 = g16[e], v2 = ldv[e];
        #pragma unroll
        for (int off = 16; off; off >>= 1) {
            v1 += __shfl_down_sync(0xffffffffu, v1, off);
            v2 += __shfl_down_sync(0xffffffffu, v2, off);
        }
        if (lane == 0) {
            atomicAdd(&g_importance[e], v1);
            atomicAdd(&g_load[e], v2);
        }
    }
}

// ---------------- kernel 3: loss ---------------------------------------------
__global__ void k_loss(float* __restrict__ out)
{
    if (threadIdx.x == 0 && blockIdx.x == 0) {
        float mi = 0.f, ml = 0.f;
        for (int e = 0; e < En; e++) { mi += g_importance[e]; ml += g_load[e]; }
        mi *= (1.f / En); ml *= (1.f / En);
        float vi = 0.f, vl = 0.f;
        for (int e = 0; e < En; e++) {
            float d1 = g_importance[e] - mi; vi += d1 * d1;
            float d2 = g_load[e] - ml;       vl += d2 * d2;
        }
        vi /= (En - 1); vl /= (En - 1);
        out[(size_t)Bn * Hn] = 0.01f * (vi / (mi * mi + 1e-10f) + vl / (ml * ml + 1e-10f));
    }
}

// ---------------- kernel 5: B = expert_w -> tf32, tiled + swizzled -----------
__global__ __launch_bounds__(256) void k_prep_b(const float* __restrict__ ew)
{
#if HAS_TC
    int h64 = blockIdx.x;   // 0..15 -> 64 h rows
    int kc  = blockIdx.y;   // 0..255 -> k chunk
    __shared__ float ts[64][65];   // [h-local][k-local]
    int tid = threadIdx.x;
    int kl = tid >> 4;
    int h4 = (tid & 15) * 4;
    #pragma unroll
    for (int r = 0; r < 4; r++) {
        int kk = kl + r * 16;
        float4 v = *(const float4*)(ew + (size_t)(kc * 64 + kk) * Hn + h64 * 64 + h4);
        ts[h4 + 0][kk] = v.x; ts[h4 + 1][kk] = v.y;
        ts[h4 + 2][kk] = v.z; ts[h4 + 3][kk] = v.w;
    }
    __syncthreads();
    #pragma unroll
    for (int r2 = 0; r2 < 2; r2++) {
        int it = tid + r2 * 256;   // 0..511
        int hl = it >> 3, kg = it & 7;    // 8 k-cols per item
        uint32_t w[8];
        #pragma unroll
        for (int j = 0; j < 8; j++) w[j] = f2tf(ts[hl][kg * 8 + j]);
        int hg = h64 * 64 + hl;
        int ht = hg >> 8, rr = hg & 255;
        int sub = kg >> 2;
        uint32_t bytec = (uint32_t)((kg & 3) * 32);
        size_t base = ((size_t)(ht * TC_NCH + kc)) * TC_BCHUNK + (size_t)sub * 32768;
        *(uint4*)(g_Bt + base + SWZ((uint32_t)(rr * 128) + bytec))      = make_uint4(w[0], w[1], w[2], w[3]);
        *(uint4*)(g_Bt + base + SWZ((uint32_t)(rr * 128) + bytec + 16)) = make_uint4(w[4], w[5], w[6], w[7]);
    }
#endif
}

__global__ __launch_bounds__(256) void k_prep_bb(const float* __restrict__ eb)
{
#if HAS_TC
    int ht = blockIdx.x;       // 0..3
    int row = threadIdx.x;     // h within 256-tile
    int hg = ht * 256 + row;
    #pragma unroll
    for (int kg = 0; kg < 8; kg++) {
        uint32_t w[8];
        #pragma unroll
        for (int j = 0; j < 8; j++) {
            int c = kg * 8 + j;
            w[j] = (c < 16) ? f2tf(eb[c * Hn + hg]) : 0u;
        }
        int sub = kg >> 2;
        uint32_t bytec = (uint32_t)((kg & 3) * 32);
        size_t base = ((size_t)(ht * TC_NCH + 256)) * TC_BCHUNK + (size_t)sub * 32768;
        *(uint4*)(g_Bt + base + SWZ((uint32_t)(row * 128) + bytec))      = make_uint4(w[0], w[1], w[2], w[3]);
        *(uint4*)(g_Bt + base + SWZ((uint32_t)(row * 128) + bytec + 16)) = make_uint4(w[4], w[5], w[6], w[7]);
    }
#endif
}

// =============================================================================
//  kernel 7 (tc path): fused tf32 GEMM, 2-CTA B multicast
//  A chunk (32KB) = [sub(2)][128 rows x 32 tf32 cols SW128]; converted in-SM.
//  B chunk (64KB) = [sub(2)][256 rows x 32 tf32 cols SW128]; multicast halves.
// =============================================================================
#define TC_MT 128
#define TC_NT 256
#define SM_A(s)   (1024u + (uint32_t)(s) * 32768u)
#define SM_B(s)   (66560u + (uint32_t)(s) * 65536u)
#define SM_GS     197632u
#define GEMM2_SMEM 206848

__global__ __launch_bounds__(320, 1) __cluster_dims__(1, 2, 1)
void k_gemm_tc2(const float* __restrict__ x, float* __restrict__ out)
{
#if HAS_TC
    extern __shared__ unsigned char smc[];
    const uint32_t sb = smem_u32(smc);
    const uint32_t mb_af0 = sb + 0,  mb_af1 = sb + 8;
    const uint32_t mb_bf0 = sb + 16, mb_bf1 = sb + 24;
    const uint32_t mb_dn0 = sb + 32, mb_dn1 = sb + 40;
    const uint32_t mb_done = sb + 48;
    const uint32_t tptr    = sb + 64;
    float* gs = (float*)(smc + SM_GS);

    const int tid = threadIdx.x, wid = tid >> 5, lane = tid & 31;
    const int nt = blockIdx.x, mt = blockIdx.y;
    const int bM = mt * TC_MT;
    const uint32_t rank = ctarank();

    if (tid == 0) {
        MBAR_INIT(mb_af0, 256); MBAR_INIT(mb_af1, 256);
        MBAR_INIT(mb_bf0, 1);   MBAR_INIT(mb_bf1, 1);
        MBAR_INIT(mb_dn0, 2);   MBAR_INIT(mb_dn1, 2);
        MBAR_INIT(mb_done, 2);
    }
    for (int i = tid; i < TC_MT * En; i += 320) {
        int r = i >> 4, e = i & 15;
        gs[r * 17 + e] = g_gates[(size_t)(bM + r) * En + e];
    }
    __syncthreads();
    if (wid == 9) {
        asm volatile("tcgen05.alloc.cta_group::1.sync.aligned.shared::cta.b32 [%0], %1;" :: "r"(tptr), "r"((uint32_t)TC_NT) : "memory");
        asm volatile("tcgen05.relinquish_alloc_permit.cta_group::1.sync.aligned;");
    }
    __syncthreads();
    CLUSTER_SYNC();
    uint32_t tmem;
    asm volatile("ld.shared.b32 %0, [%1];" : "=r"(tmem) : "r"(tptr));

    const uint64_t DESC_BASE =
        (uint64_t(2) << 61) | (uint64_t(1) << 46) | (uint64_t(64) << 32) | (uint64_t(1) << 16);
    // idesc: F32 accum(1<<4), atype TF32(2<<7), btype TF32(2<<10), N=256, M=128
    const uint32_t GIDESC = (1u<<4) | (2u<<7) | (2u<<10) | ((TC_NT/8u)<<17) | ((TC_MT/16u)<<24);

    if (tid < 256) {
        // ---------------- A converters: tf32 into [sub][128x128B] ----------
        const int r    = tid >> 1;          // row 0..127
        const int half = tid & 1;           // sub-chunk (32-col group)
        const float* xp = x + (size_t)(bM + r) * Dn + (size_t)half * 32;
        uint32_t dph[2] = {0, 0};
        int i = 0;
        for (int db = 0; db < 16; db++) {
            float xr[32];
            const float4* xv = (const float4*)(xp + db * 64);
            #pragma unroll
            for (int q = 0; q < 8; q++) {
                float4 f = xv[q];
                xr[4*q] = f.x; xr[4*q+1] = f.y; xr[4*q+2] = f.z; xr[4*q+3] = f.w;
            }
            for (int e = 0; e < 16; e++, i++) {
                int s = i & 1;
                uint32_t mdn = s ? mb_dn1 : mb_dn0;
                uint32_t maf = s ? mb_af1 : mb_af0;
                if (i >= 2) { MBAR_WAIT(mdn, dph[s]); dph[s] ^= 1; }
                float g = gs[r * 17 + e];
                uint32_t w[32];
                #pragma unroll
                for (int j = 0; j < 32; j++) w[j] = f2tf(g * xr[j]);
                unsigned char* ap = smc + SM_A(s) + half * 16384;
                #pragma unroll
                for (int q = 0; q < 8; q++) {
                    uint32_t off = SWZ((uint32_t)(r * 128 + q * 16));
                    *(uint4*)(ap + off) = make_uint4(w[4*q], w[4*q+1], w[4*q+2], w[4*q+3]);
                }
                asm volatile("fence.proxy.async.shared::cta;" ::: "memory");
                MBAR_ARRIVE(maf);
            }
        }
        // bias chunk (i == 256): global cols 0..15 = gates
        {
            int s = 0;
            MBAR_WAIT(mb_dn0, dph[0]); dph[0] ^= 1;
            uint32_t w[32];
            #pragma unroll
            for (int j = 0; j < 32; j++) {
                int c = half * 32 + j;
                w[j] = (c < 16) ? f2tf(gs[r * 17 + c]) : 0u;
            }
            unsigned char* ap = smc + SM_A(s) + half * 16384;
            #pragma unroll
            for (int q = 0; q < 8; q++) {
                uint32_t off = SWZ((uint32_t)(r * 128 + q * 16));
                *(uint4*)(ap + off) = make_uint4(w[4*q], w[4*q+1], w[4*q+2], w[4*q+3]);
            }
            asm volatile("fence.proxy.async.shared::cta;" ::: "memory");
            MBAR_ARRIVE(mb_af0);
        }
    } else if (tid == 256) {
        // ---------------- B producer: multicast cooperative sub-slices ------
        const unsigned char* pBt = g_Bt + (size_t)nt * TC_NCH * TC_BCHUNK;
        const uint32_t hoff = rank * 32768u;    // this CTA's sub-chunk
        uint32_t dph[2] = {0, 0};
        for (int i = 0; i <= 256; i++) {
            int s = i & 1;
            uint32_t mdn = s ? mb_dn1 : mb_dn0;
            uint32_t mbf = s ? mb_bf1 : mb_bf0;
            if (i >= 2) { MBAR_WAIT(mdn, dph[s]); dph[s] ^= 1; }
            int cB = (i < 256) ? ((i & 15) * 16 + (i >> 4)) : 256;
            MBAR_EXPECT_TX(mbf, TC_BCHUNK);   // 2 slices (local + peer) = 64KB
            bulk_g2s_mc(sb + SM_B(s) + hoff, pBt + (size_t)cB * TC_BCHUNK + hoff, 32768u, mbf, 3);
        }
    } else if (tid == 288) {
        // ---------------- MMA issuer (kind::tf32, 8 dispatches/chunk) -------
        uint32_t aph[2] = {0, 0}, bph[2] = {0, 0};
        uint32_t acc = 0;
        for (int i = 0; i <= 256; i++) {
            int s = i & 1;
            uint32_t maf = s ? mb_af1 : mb_af0;
            uint32_t mbf = s ? mb_bf1 : mb_bf0;
            MBAR_WAIT(maf, aph[s]); aph[s] ^= 1;
            MBAR_WAIT(mbf, bph[s]); bph[s] ^= 1;
            uint64_t da = DESC_BASE | ((uint64_t)((sb + SM_A(s)) >> 4) & 0x3FFF);
            uint64_t db = DESC_BASE | ((uint64_t)((sb + SM_B(s)) >> 4) & 0x3FFF);
            #pragma unroll
            for (int ks = 0; ks < 8; ks++) {
                uint64_t dak = da + (uint64_t)(ks >> 2) * 1024 + (uint64_t)(ks & 3) * 2;
                uint64_t dbk = db + (uint64_t)(ks >> 2) * 2048 + (uint64_t)(ks & 3) * 2;
                asm volatile("{ .reg .pred p; setp.ne.u32 p, %5, 0;\n"
                    "tcgen05.mma.cta_group::1.kind::tf32 [%0], %1, %2, %3, {%4,%4,%4,%4}, p; }"
                    :: "r"(tmem), "l"(dak), "l"(dbk), "r"(GIDESC), "r"(0u), "r"(acc) : "memory");
                acc = 1;
            }
            uint32_t mtarget = (i == 256) ? mb_done : (s ? mb_dn1 : mb_dn0);
            asm volatile(
                "tcgen05.commit.cta_group::1.mbarrier::arrive::one.shared::cluster.multicast::cluster.b64 [%0], %1;"
                :: "r"(mtarget), "h"((uint16_t)3) : "memory");
        }
    }

    // ---------------- epilogue -----------------------------------------------
    MBAR_WAIT(mb_done, 0);
    asm volatile("tcgen05.fence::after_thread_sync;" ::: "memory");

    if (wid < 4) {
        int row = bM + wid * 32 + lane;
        float* orow = out + (size_t)row * Hn + nt * TC_NT;
        #pragma unroll
        for (int cc = 0; cc < 8; cc++) {
            uint32_t r[32];
            asm volatile(
                "tcgen05.ld.sync.aligned.32x32b.x32.b32 "
                "{%0,%1,%2,%3,%4,%5,%6,%7,%8,%9,%10,%11,%12,%13,%14,%15,"
                "%16,%17,%18,%19,%20,%21,%22,%23,%24,%25,%26,%27,%28,%29,%30,%31}, [%32];"
                : "=r"(r[0]),"=r"(r[1]),"=r"(r[2]),"=r"(r[3]),"=r"(r[4]),"=r"(r[5]),"=r"(r[6]),"=r"(r[7]),
                  "=r"(r[8]),"=r"(r[9]),"=r"(r[10]),"=r"(r[11]),"=r"(r[12]),"=r"(r[13]),"=r"(r[14]),"=r"(r[15]),
                  "=r"(r[16]),"=r"(r[17]),"=r"(r[18]),"=r"(r[19]),"=r"(r[20]),"=r"(r[21]),"=r"(r[22]),"=r"(r[23]),
                  "=r"(r[24]),"=r"(r[25]),"=r"(r[26]),"=r"(r[27]),"=r"(r[28]),"=r"(r[29]),"=r"(r[30]),"=r"(r[31])
                : "r"(tmem + cc * 32));
            asm volatile("tcgen05.wait::ld.sync.aligned;" ::: "memory");
            #pragma unroll
            for (int q = 0; q < 8; q++) {
                *(float4*)(orow + cc * 32 + q * 4) = make_float4(
                    __uint_as_float(r[q*4+0]), __uint_as_float(r[q*4+1]),
                    __uint_as_float(r[q*4+2]), __uint_as_float(r[q*4+3]));
            }
        }
    }
    __syncthreads();
    if (wid == 9)
        asm volatile("tcgen05.dealloc.cta_group::1.sync.aligned.b32 %0, %1;" :: "r"(tmem), "r"((uint32_t)TC_NT));
    CLUSTER_SYNC();
#endif
}

// =============================================================================
//  PATH B: tf32 mma.sync GEMM fallback (base-target legal)
// =============================================================================
#define BM 128
#define BN 128
#define BK 32
#define STAGES 4
#define ASTR 44
#define BSTR 136
#define GSTR 17
#define A_ST_FLT (BM * ASTR)
#define B_ST_FLT (BK * BSTR)
#define NTILES (En * Dn / BK)

__global__ __launch_bounds__(256, 1) void k_gemm_mma(
    const float* __restrict__ x, const float* __restrict__ ew,
    const float* __restrict__ eb, float* __restrict__ out)
{
    if (g_tc) return;

    extern __shared__ float sm[];
    float* As  = sm;
    float* Bs  = sm + STAGES * A_ST_FLT;
    float* gs  = Bs + STAGES * B_ST_FLT;
    float* ebs = gs + BM * GSTR;

    const int tid  = threadIdx.x;
    const int lane = tid & 31;
    const int wid  = tid >> 5;
    const int wm   = wid >> 2;
    const int wn   = wid & 3;
    const int grp  = lane >> 2;
    const int qid  = lane & 3;
    const int bM = blockIdx.y * BM;
    const int bN = blockIdx.x * BN;

    for (int i = tid; i < BM * En; i += 256) {
        int r = i >> 4, e = i & 15;
        gs[r * GSTR + e] = g_gates[(size_t)(bM + r) * En + e];
    }
    for (int i = tid; i < En * BN; i += 256) {
        int e = i >> 7, c = i & 127;
        ebs[e * BN + c] = eb[(size_t)e * Hn + bN + c];
    }

    const uint32_t sbase = smem_u32(sm);
    const int ar = tid >> 1, ac = (tid & 1) * 4;
    const int bk0 = tid >> 5, bc0 = (tid & 31) * 4;
    const uint32_t adst0 = sbase + (uint32_t)(ar * ASTR + ac) * 4u;
    const uint32_t bdst0 = sbase + (uint32_t)(STAGES * A_ST_FLT + bk0 * BSTR + bc0) * 4u;

#define LOAD_TILE(kt, s) do {                                                   \
        int _d0 = ((kt) * BK) & (Dn - 1);                                       \
        cpa16(adst0 + (uint32_t)((s) * A_ST_FLT * 4),                           \
              x + (size_t)(bM + ar) * Dn + _d0 + ac);                           \
        const float* _bw = ew + (size_t)((kt) * BK + bk0) * Hn + bN + bc0;      \
        uint32_t _bd = bdst0 + (uint32_t)((s) * B_ST_FLT * 4);                  \
        cpa16(_bd,                      _bw);                                   \
        cpa16(_bd + 8u*BSTR*4u,         _bw + (size_t)8  * Hn);                 \
        cpa16(_bd + 16u*BSTR*4u,        _bw + (size_t)16 * Hn);                 \
        cpa16(_bd + 24u*BSTR*4u,        _bw + (size_t)24 * Hn);                 \
    } while (0)

    #pragma unroll
    for (int s = 0; s < STAGES - 1; s++) { LOAD_TILE(s, s); CPA_COMMIT(); }

    float acc[4][4][4];
    #pragma unroll
    for (int mi = 0; mi < 4; mi++)
        #pragma unroll
        for (int ni = 0; ni < 4; ni++)
            #pragma unroll
            for (int q = 0; q < 4; q++) acc[mi][ni][q] = 0.f;

    const int aoff = (wm * 64 + grp) * ASTR + qid;
    const int boff = qid * BSTR + wn * 32 + grp;

    float g0[4], g1[4];
    __syncthreads();

    for (int kt = 0; kt < NTILES; kt++) {
        CPA_WAIT2();
        __syncthreads();

        if ((kt & 31) == 0) {
            int e = kt >> 5;
            #pragma unroll
            for (int mi = 0; mi < 4; mi++) {
                g0[mi] = gs[(wm * 64 + mi * 16 + grp) * GSTR + e];
                g1[mi] = gs[(wm * 64 + mi * 16 + grp + 8) * GSTR + e];
            }
        }

        int nk = kt + STAGES - 1;
        if (nk < NTILES) LOAD_TILE(nk, nk & (STAGES - 1));
        CPA_COMMIT();

        const float* Ap = As + (kt & (STAGES - 1)) * A_ST_FLT + aoff;
        const float* Bp = Bs + (kt & (STAGES - 1)) * B_ST_FLT + boff;

        #pragma unroll
        for (int ks = 0; ks < 4; ks++) {
            uint32_t bf[4][2];
            #pragma unroll
            for (int ni = 0; ni < 4; ni++) {
                bf[ni][0] = f2tf(Bp[(ks * 8) * BSTR + ni * 8]);
                bf[ni][1] = f2tf(Bp[(ks * 8 + 4) * BSTR + ni * 8]);
            }
            #pragma unroll
            for (int mi = 0; mi < 4; mi++) {
                const float* ab = Ap + mi * 16 * ASTR + ks * 8;
                uint32_t a0 = f2tf(g0[mi] * ab[0]);
                uint32_t a1 = f2tf(g1[mi] * ab[8 * ASTR]);
                uint32_t a2 = f2tf(g0[mi] * ab[4]);
                uint32_t a3 = f2tf(g1[mi] * ab[8 * ASTR + 4]);
                #pragma unroll
                for (int ni = 0; ni < 4; ni++)
                    mma_tf32(acc[mi][ni], a0, a1, a2, a3, bf[ni][0], bf[ni][1]);
            }
        }
    }

    #pragma unroll
    for (int mi = 0; mi < 4; mi++) {
        int r0 = wm * 64 + mi * 16 + grp;
        #pragma unroll
        for (int e = 0; e < En; e++) {
            float ge0 = gs[r0 * GSTR + e];
            float ge1 = gs[(r0 + 8) * GSTR + e];
            #pragma unroll
            for (int ni = 0; ni < 4; ni++) {
                int c0 = wn * 32 + ni * 8 + 2 * qid;
                float b0v = ebs[e * BN + c0];
                float b1v = ebs[e * BN + c0 + 1];
                acc[mi][ni][0] = fmaf(ge0, b0v, acc[mi][ni][0]);
                acc[mi][ni][1] = fmaf(ge0, b1v, acc[mi][ni][1]);
                acc[mi][ni][2] = fmaf(ge1, b0v, acc[mi][ni][2]);
                acc[mi][ni][3] = fmaf(ge1, b1v, acc[mi][ni][3]);
            }
        }
    }

    #pragma unroll
    for (int mi = 0; mi < 4; mi++) {
        int r0 = bM + wm * 64 + mi * 16 + grp;
        #pragma unroll
        for (int ni = 0; ni < 4; ni++) {
            int c0 = bN + wn * 32 + ni * 8 + 2 * qid;
            *(float2*)(out + (size_t)r0 * Hn + c0)       = make_float2(acc[mi][ni][0], acc[mi][ni][1]);
            *(float2*)(out + (size_t)(r0 + 8) * Hn + c0) = make_float2(acc[mi][ni][2], acc[mi][ni][3]);
        }
    }
#undef LOAD_TILE
}

// ---------------- launch ------------------------------------------------------
extern "C" void kernel_launch(void* const* d_in, const int* in_sizes, int n_in,
                              void* d_out, int out_size)
{
    const float* x     = (const float*)d_in[0];
    const float* wg    = (const float*)d_in[1];
    const float* wn    = (const float*)d_in[2];
    const float* ew    = (const float*)d_in[3];
    const float* eb    = (const float*)d_in[4];
    const float* noise = (const float*)d_in[5];
    float* out = (float*)d_out;

    static const int MMA_SMEM = (STAGES * (A_ST_FLT + B_ST_FLT) + BM * GSTR + En * BN) * 4;
    cudaFuncSetAttribute(k_gemm_tc2, cudaFuncAttributeMaxDynamicSharedMemorySize, GEMM2_SMEM);
    cudaFuncSetAttribute(k_gemm_mma, cudaFuncAttributeMaxDynamicSharedMemorySize, MMA_SMEM);

    k_init<<<1, 32>>>();
    k_logits<<<Bn / 8, 1024>>>(x, wg, wn, noise);
    k_gate<<<Bn / 256, 256>>>();
    k_loss<<<1, 32>>>(out);

    // tcgen05 path (no-ops when compiled for base sm_103)
    k_prep_b<<<dim3(16, 256), 256>>>(ew);
    k_prep_bb<<<4, 256>>>(eb);
    k_gemm_tc2<<<dim3(Hn / TC_NT, Bn / TC_MT), 320, GEMM2_SMEM>>>(x, out);

    // mma.sync fallback (early-exits if tc path is live)
    k_gemm_mma<<<dim3(Hn / BN, Bn / BM), 256, MMA_SMEM>>>(x, ew, eb, out);
}